// round 1
// baseline (speedup 1.0000x reference)
#include <cuda_runtime.h>

#define NN 100000
#define EE 800000
#define FD 128

// ---------------- scratch (device globals; no allocations allowed) ----------
__device__ float g_bufA[NN * FD];
__device__ float g_bufB[NN * FD];
__device__ float g_agg [NN * FD];
__device__ float g_invdeg[NN];

// ---------------- packed f32x2 helpers (Blackwell FFMA2 path) --------------
__device__ __forceinline__ unsigned long long pack2(float lo, float hi) {
    union { float2 f; unsigned long long u; } c;
    c.f = make_float2(lo, hi);
    return c.u;
}
__device__ __forceinline__ float2 unpack2(unsigned long long v) {
    union { float2 f; unsigned long long u; } c;
    c.u = v;
    return c.f;
}
__device__ __forceinline__ unsigned long long dup2(float x) { return pack2(x, x); }
__device__ __forceinline__ void fma2(unsigned long long& d, unsigned long long a,
                                     unsigned long long b) {
    asm("fma.rn.f32x2 %0, %1, %2, %0;" : "+l"(d) : "l"(a), "l"(b));
}

// ---------------- GEMM: out[i][j] = act(sum_k in[i][k]*W[j][k] + b[j]) ------
// in: [N,128] row-major, W: [NOUT,128] row-major, out: [N,NOUT]
// 128 threads, each computes 8 rows x 8 cols; rows packed in pairs into f32x2
// accumulators so the x operand comes packed straight out of LDS.128.
template<int NOUT, bool RELU>
__global__ void __launch_bounds__(128, 1)
gemm_kernel(const float* __restrict__ A, const float* __restrict__ W,
            const float* __restrict__ bias, float* __restrict__ out, int N)
{
    constexpr int TX  = NOUT / 8;     // 16 (NOUT=128) or 8 (NOUT=64)
    constexpr int TY  = 128 / TX;     // 8 or 16
    constexpr int MT  = TY * 8;       // 64 or 128 rows per block
    constexpr int XST = MT + 4;       // padded stride for x tile

    extern __shared__ float sm[];
    float* Wt = sm;                   // [128][NOUT]  (k-major W^T)
    float* Xs = sm + 128 * NOUT;      // [128][XST]   (k-major x tile)

    const int tid  = threadIdx.x;
    const int tx   = tid % TX;
    const int ty   = tid / TX;
    const int row0 = blockIdx.x * MT;

    // Load W transposed. STS is coalesced (lanes -> consecutive j); the LDG is
    // strided but W is 64KB and L2-hot across all blocks.
    #pragma unroll 4
    for (int idx = tid; idx < NOUT * 128; idx += 128) {
        int j = idx % NOUT;
        int k = idx / NOUT;
        Wt[k * NOUT + j] = W[j * 128 + k];
    }

    // Load x tile transposed: coalesced float4 LDG, lane-rotated STS to cut
    // bank conflicts from 16-way to 8-way.
    const int rot = tid & 3;
    #pragma unroll 4
    for (int idx = tid; idx < MT * 32; idx += 128) {
        int r   = idx >> 5;
        int c4  = idx & 31;
        int row = row0 + r;
        float4 v = make_float4(0.f, 0.f, 0.f, 0.f);
        if (row < N) v = reinterpret_cast<const float4*>(A)[row * 32 + c4];
        #pragma unroll
        for (int i = 0; i < 4; ++i) {
            int ii = (i + rot) & 3;
            float val = (ii == 0) ? v.x : (ii == 1) ? v.y : (ii == 2) ? v.z : v.w;
            Xs[(4 * c4 + ii) * XST + r] = val;
        }
    }
    __syncthreads();

    unsigned long long acc[4][8];
    #pragma unroll
    for (int rp = 0; rp < 4; ++rp)
        #pragma unroll
        for (int c = 0; c < 8; ++c) acc[rp][c] = 0ULL;

    const float4* WtV = reinterpret_cast<const float4*>(Wt + 8 * tx);
    const float4* XsV = reinterpret_cast<const float4*>(Xs + 8 * ty);

    #pragma unroll 4
    for (int k = 0; k < 128; ++k) {
        float4 w0 = WtV[k * (NOUT / 4)];
        float4 w1 = WtV[k * (NOUT / 4) + 1];
        float4 x0 = XsV[k * (XST / 4)];
        float4 x1 = XsV[k * (XST / 4) + 1];
        unsigned long long xp0 = pack2(x0.x, x0.y);
        unsigned long long xp1 = pack2(x0.z, x0.w);
        unsigned long long xp2 = pack2(x1.x, x1.y);
        unsigned long long xp3 = pack2(x1.z, x1.w);
        unsigned long long wd0 = dup2(w0.x), wd1 = dup2(w0.y), wd2 = dup2(w0.z), wd3 = dup2(w0.w);
        unsigned long long wd4 = dup2(w1.x), wd5 = dup2(w1.y), wd6 = dup2(w1.z), wd7 = dup2(w1.w);
        unsigned long long wd[8] = {wd0, wd1, wd2, wd3, wd4, wd5, wd6, wd7};
        #pragma unroll
        for (int c = 0; c < 8; ++c) {
            fma2(acc[0][c], wd[c], xp0);
            fma2(acc[1][c], wd[c], xp1);
            fma2(acc[2][c], wd[c], xp2);
            fma2(acc[3][c], wd[c], xp3);
        }
    }

    float bc[8];
    #pragma unroll
    for (int c = 0; c < 8; ++c) bc[c] = bias[8 * tx + c];

    #pragma unroll
    for (int rp = 0; rp < 4; ++rp) {
        #pragma unroll
        for (int h = 0; h < 2; ++h) {
            int r = row0 + 8 * ty + 2 * rp + h;
            if (r < N) {
                float o[8];
                #pragma unroll
                for (int c = 0; c < 8; ++c) {
                    float2 p = unpack2(acc[rp][c]);
                    float v  = (h == 0 ? p.x : p.y) + bc[c];
                    o[c] = RELU ? fmaxf(v, 0.f) : v;
                }
                float4* op = reinterpret_cast<float4*>(out + (size_t)r * NOUT + 8 * tx);
                op[0] = make_float4(o[0], o[1], o[2], o[3]);
                op[1] = make_float4(o[4], o[5], o[6], o[7]);
            }
        }
    }
}

// ---------------- aggregation helpers ---------------------------------------
__global__ void zero_kernel(float4* p, int n4) {
    int i = blockIdx.x * blockDim.x + threadIdx.x;
    if (i < n4) p[i] = make_float4(0.f, 0.f, 0.f, 0.f);
}

__global__ void deg_kernel(const int* __restrict__ dst, int E, float* __restrict__ deg) {
    int i = blockIdx.x * blockDim.x + threadIdx.x;
    if (i < E) atomicAdd(&deg[dst[i]], 1.0f);
}

__global__ void invdeg_kernel(float* deg, int n) {
    int i = blockIdx.x * blockDim.x + threadIdx.x;
    if (i < n) deg[i] = 1.0f / fmaxf(deg[i], 1.0f);
}

// one warp per edge: gather 128 floats from src row, atomic-add into dst row
__global__ void scatter_kernel(const float* __restrict__ h, const int* __restrict__ src,
                               const int* __restrict__ dst, float* __restrict__ agg, int E)
{
    int gt   = blockIdx.x * blockDim.x + threadIdx.x;
    int e    = gt >> 5;
    int lane = threadIdx.x & 31;
    if (e >= E) return;
    int s = __ldg(src + e);
    int d = __ldg(dst + e);
    float4 v = reinterpret_cast<const float4*>(h + (size_t)s * FD)[lane];
    float* p = agg + (size_t)d * FD + lane * 4;
    atomicAdd(p + 0, v.x);
    atomicAdd(p + 1, v.y);
    atomicAdd(p + 2, v.z);
    atomicAdd(p + 3, v.w);
}

// out[i] = base[i] + agg[i] * invdeg[node]
__global__ void combine_kernel(const float* __restrict__ base, const float* __restrict__ agg,
                               const float* __restrict__ invd, float* __restrict__ out, int N)
{
    int idx = blockIdx.x * blockDim.x + threadIdx.x;   // over N*32 float4s
    if (idx >= N * 32) return;
    int node = idx >> 5;
    float s  = invd[node];
    float4 b = reinterpret_cast<const float4*>(base)[idx];
    float4 a = reinterpret_cast<const float4*>(agg)[idx];
    reinterpret_cast<float4*>(out)[idx] =
        make_float4(b.x + a.x * s, b.y + a.y * s, b.z + a.z * s, b.w + a.w * s);
}

// ---------------- launch -----------------------------------------------------
extern "C" void kernel_launch(void* const* d_in, const int* in_sizes, int n_in,
                              void* d_out, int out_size)
{
    const float* x   = (const float*)d_in[0];
    const int*   src = (const int*)  d_in[1];
    const int*   dst = (const int*)  d_in[2];
    const float* W1  = (const float*)d_in[3];
    const float* b1  = (const float*)d_in[4];
    const float* W2  = (const float*)d_in[5];
    const float* b2  = (const float*)d_in[6];
    const float* W3  = (const float*)d_in[7];
    const float* b3  = (const float*)d_in[8];
    const float* Wo1 = (const float*)d_in[9];
    const float* bo1 = (const float*)d_in[10];
    const float* Wo2 = (const float*)d_in[11];
    const float* bo2 = (const float*)d_in[12];
    float* out = (float*)d_out;

    const int N = in_sizes[0] / FD;    // 100000
    const int E = in_sizes[1];         // 800000

    float *bufA, *bufB, *agg, *invd;
    cudaGetSymbolAddress((void**)&bufA, g_bufA);
    cudaGetSymbolAddress((void**)&bufB, g_bufB);
    cudaGetSymbolAddress((void**)&agg,  g_agg);
    cudaGetSymbolAddress((void**)&invd, g_invdeg);

    const int smem128 = (128 * 128 + 128 * (64 + 4))  * (int)sizeof(float);  // 100352
    const int smem64  = (128 * 64  + 128 * (128 + 4)) * (int)sizeof(float);  // 100352
    cudaFuncSetAttribute(gemm_kernel<128, true >, cudaFuncAttributeMaxDynamicSharedMemorySize, smem128);
    cudaFuncSetAttribute(gemm_kernel<128, false>, cudaFuncAttributeMaxDynamicSharedMemorySize, smem128);
    cudaFuncSetAttribute(gemm_kernel<64,  false>, cudaFuncAttributeMaxDynamicSharedMemorySize, smem64);

    const int g128 = (N + 63)  / 64;    // 64-row tiles
    const int g64  = (N + 127) / 128;   // 128-row tiles for NOUT=64
    const int zg   = (N * 32 + 255) / 256;
    const int cg   = (N * 32 + 255) / 256;
    const int sg   = (E * 32 + 255) / 256;

    // degrees (dst-only; recomputed each call for determinism)
    zero_kernel<<<(N / 4 + 255) / 256, 256>>>((float4*)invd, N / 4);
    deg_kernel<<<(E + 255) / 256, 256>>>(dst, E, invd);
    invdeg_kernel<<<(N + 255) / 256, 256>>>(invd, N);

    // x2 = lin(relu(lin(x,W1,b1)),W2,b2)
    gemm_kernel<128, true ><<<g128, 128, smem128>>>(x,    W1, b1, bufA, N);
    gemm_kernel<128, false><<<g128, 128, smem128>>>(bufA, W2, b2, bufB, N);

    // h = x2 + mean_agg(x2)
    zero_kernel<<<zg, 256>>>((float4*)agg, N * 32);
    scatter_kernel<<<sg, 256>>>(bufB, src, dst, agg, E);
    combine_kernel<<<cg, 256>>>(bufB, agg, invd, bufA, N);

    // h = lin(relu(lin(h,W1,b1)),W2,b2)   (g_agg reused as temp, re-zeroed later)
    gemm_kernel<128, true ><<<g128, 128, smem128>>>(bufA, W1, b1, agg,  N);
    gemm_kernel<128, false><<<g128, 128, smem128>>>(agg,  W2, b2, bufB, N);

    // h = relu(lin(h,W3,b3))
    gemm_kernel<128, true ><<<g128, 128, smem128>>>(bufB, W3, b3, bufA, N);

    // h = h + mean_agg(h)
    zero_kernel<<<zg, 256>>>((float4*)agg, N * 32);
    scatter_kernel<<<sg, 256>>>(bufA, src, dst, agg, E);
    combine_kernel<<<cg, 256>>>(bufA, agg, invd, bufB, N);

    // h = relu(lin(h,W3,b3)); h = relu(lin(h,Wo1,bo1)); out = lin(h,Wo2,bo2)
    gemm_kernel<128, true ><<<g128, 128, smem128>>>(bufB, W3,  b3,  bufA, N);
    gemm_kernel<128, true ><<<g128, 128, smem128>>>(bufA, Wo1, bo1, bufB, N);
    gemm_kernel<64,  false><<<g64,  128, smem64 >>>(bufB, Wo2, bo2, out,  N);
}

// round 3
// speedup vs baseline: 2.2205x; 2.2205x over previous
#include <cuda_runtime.h>
#include <cstdint>

#define NN 100000
#define EE 800000
#define FD 128

// ---------------- scratch (device globals; no allocations allowed) ----------
__device__ float g_bufA[NN * FD];
__device__ float g_bufB[NN * FD];
__device__ float g_agg [NN * FD];
__device__ float g_invdeg[NN];

// ---------------- tf32 split helpers -----------------------------------------
__device__ __forceinline__ uint32_t tf32_hi(float x) {
    uint32_t h;
    asm("cvt.rna.tf32.f32 %0, %1;" : "=r"(h) : "f"(x));
    return h;
}
__device__ __forceinline__ void tf32_hilo(float x, uint32_t& h, uint32_t& l) {
    asm("cvt.rna.tf32.f32 %0, %1;" : "=r"(h) : "f"(x));
    float r = x - __uint_as_float(h);       // exact in fp32
    asm("cvt.rna.tf32.f32 %0, %1;" : "=r"(l) : "f"(r));
}
__device__ __forceinline__ uint32_t tf32_lo(float x) {
    uint32_t h, l;
    tf32_hilo(x, h, l);
    return l;
}

#define MMA_TF32(d, a, b)                                                     \
    asm volatile(                                                             \
        "mma.sync.aligned.m16n8k8.row.col.f32.tf32.tf32.f32 "                 \
        "{%0,%1,%2,%3}, {%4,%5,%6,%7}, {%8,%9}, {%0,%1,%2,%3};"               \
        : "+f"((d)[0]), "+f"((d)[1]), "+f"((d)[2]), "+f"((d)[3])              \
        : "r"((a)[0]), "r"((a)[1]), "r"((a)[2]), "r"((a)[3]),                 \
          "r"((b)[0]), "r"((b)[1]))

// ---------------- split-TF32 mma.sync GEMM ------------------------------------
// out[i][j] = act( sum_k in[i][k] * W[j][k] + b[j] )
// CTA: 256 threads = 8 warps (4 m x 2 n). Tile: 128 rows x NOUT cols, K=128.
// 3 effective passes: Ah*Bh, Ah*Bl (fused, reusing A frags), then Al*Bh.
template<int NOUT, bool RELU>
__global__ void __launch_bounds__(256, 1)
gemm_mma(const float* __restrict__ A, const float* __restrict__ W,
         const float* __restrict__ bias, float* __restrict__ out, int N)
{
    constexpr int LDA = 132;              // padded float stride (conflict-free frags)
    constexpr int NI  = NOUT / 16;        // n-frags (8 cols each) per warp: 8 or 4
    extern __shared__ float sm[];
    float* As = sm;                        // [128][LDA]
    float* Ws = sm + 128 * LDA;            // [NOUT][LDA]

    const int tid  = threadIdx.x;
    const int wid  = tid >> 5;
    const int lane = tid & 31;
    const int wm   = wid & 3;              // warp row 0..3   (32 rows each)
    const int wn   = wid >> 2;             // warp col 0..1   (NOUT/2 cols each)
    const int row0 = blockIdx.x * 128;
    const int qr   = lane >> 2;            // 0..7
    const int qc   = lane & 3;             // 0..3

    // ---- stage A tile (coalesced float4, zero-fill OOB rows) ----
    #pragma unroll
    for (int it = 0; it < 16; ++it) {
        int idx = tid + it * 256;
        int r = idx >> 5, c4 = idx & 31;
        int row = row0 + r;
        float4 v = make_float4(0.f, 0.f, 0.f, 0.f);
        if (row < N) v = reinterpret_cast<const float4*>(A)[(size_t)row * 32 + c4];
        *reinterpret_cast<float4*>(As + r * LDA + c4 * 4) = v;
    }
    // ---- stage W tile ----
    #pragma unroll
    for (int it = 0; it < NOUT / 8; ++it) {
        int idx = tid + it * 256;
        int r = idx >> 5, c4 = idx & 31;
        float4 v = reinterpret_cast<const float4*>(W)[(size_t)r * 32 + c4];
        *reinterpret_cast<float4*>(Ws + r * LDA + c4 * 4) = v;
    }
    __syncthreads();

    float acc[2][NI][4];
    #pragma unroll
    for (int mi = 0; mi < 2; ++mi)
        #pragma unroll
        for (int ni = 0; ni < NI; ++ni)
            #pragma unroll
            for (int c = 0; c < 4; ++c) acc[mi][ni][c] = 0.f;

    const float* Ab = As + (wm * 32 + qr) * LDA + qc;
    const float* Bb = Ws + (wn * (NOUT / 2) + qr) * LDA + qc;

    // ---- pass 0+1: A-hi x (B-hi, B-lo) ----
    #pragma unroll 1
    for (int ks = 0; ks < 16; ++ks) {
        const int k0 = ks * 8;
        uint32_t ah[2][4];
        #pragma unroll
        for (int mi = 0; mi < 2; ++mi) {
            const float* ap = Ab + mi * 16 * LDA + k0;
            ah[mi][0] = tf32_hi(ap[0]);
            ah[mi][1] = tf32_hi(ap[8 * LDA]);
            ah[mi][2] = tf32_hi(ap[4]);
            ah[mi][3] = tf32_hi(ap[8 * LDA + 4]);
        }
        uint32_t bh[NI][2], bl[NI][2];
        #pragma unroll
        for (int ni = 0; ni < NI; ++ni) {
            const float* bp = Bb + ni * 8 * LDA + k0;
            tf32_hilo(bp[0], bh[ni][0], bl[ni][0]);
            tf32_hilo(bp[4], bh[ni][1], bl[ni][1]);
        }
        #pragma unroll
        for (int mi = 0; mi < 2; ++mi)
            #pragma unroll
            for (int ni = 0; ni < NI; ++ni)
                MMA_TF32(acc[mi][ni], ah[mi], bh[ni]);
        #pragma unroll
        for (int mi = 0; mi < 2; ++mi)
            #pragma unroll
            for (int ni = 0; ni < NI; ++ni)
                MMA_TF32(acc[mi][ni], ah[mi], bl[ni]);
    }
    // ---- pass 2: A-lo x B-hi ----
    #pragma unroll 1
    for (int ks = 0; ks < 16; ++ks) {
        const int k0 = ks * 8;
        uint32_t al[2][4];
        #pragma unroll
        for (int mi = 0; mi < 2; ++mi) {
            const float* ap = Ab + mi * 16 * LDA + k0;
            al[mi][0] = tf32_lo(ap[0]);
            al[mi][1] = tf32_lo(ap[8 * LDA]);
            al[mi][2] = tf32_lo(ap[4]);
            al[mi][3] = tf32_lo(ap[8 * LDA + 4]);
        }
        uint32_t bh[NI][2];
        #pragma unroll
        for (int ni = 0; ni < NI; ++ni) {
            const float* bp = Bb + ni * 8 * LDA + k0;
            bh[ni][0] = tf32_hi(bp[0]);
            bh[ni][1] = tf32_hi(bp[4]);
        }
        #pragma unroll
        for (int mi = 0; mi < 2; ++mi)
            #pragma unroll
            for (int ni = 0; ni < NI; ++ni)
                MMA_TF32(acc[mi][ni], al[mi], bh[ni]);
    }

    // ---- epilogue: bias + act, direct float2 stores ----
    const int rbase = row0 + wm * 32 + qr;
    const int cbase = wn * (NOUT / 2) + qc * 2;
    #pragma unroll
    for (int ni = 0; ni < NI; ++ni) {
        int c = cbase + ni * 8;
        float b0 = __ldg(bias + c), b1 = __ldg(bias + c + 1);
        #pragma unroll
        for (int mi = 0; mi < 2; ++mi) {
            int r = rbase + mi * 16;
            float v0 = acc[mi][ni][0] + b0;
            float v1 = acc[mi][ni][1] + b1;
            float v2 = acc[mi][ni][2] + b0;
            float v3 = acc[mi][ni][3] + b1;
            if (RELU) {
                v0 = fmaxf(v0, 0.f); v1 = fmaxf(v1, 0.f);
                v2 = fmaxf(v2, 0.f); v3 = fmaxf(v3, 0.f);
            }
            if (r < N)
                *reinterpret_cast<float2*>(out + (size_t)r * NOUT + c) = make_float2(v0, v1);
            if (r + 8 < N)
                *reinterpret_cast<float2*>(out + (size_t)(r + 8) * NOUT + c) = make_float2(v2, v3);
        }
    }
}

// ---------------- aggregation helpers ---------------------------------------
__global__ void zero_kernel(float4* p, int n4) {
    int i = blockIdx.x * blockDim.x + threadIdx.x;
    if (i < n4) p[i] = make_float4(0.f, 0.f, 0.f, 0.f);
}

__global__ void deg_kernel(const int* __restrict__ dst, int E, float* __restrict__ deg) {
    int i = blockIdx.x * blockDim.x + threadIdx.x;
    if (i < E) atomicAdd(&deg[dst[i]], 1.0f);
}

__global__ void invdeg_kernel(float* deg, int n) {
    int i = blockIdx.x * blockDim.x + threadIdx.x;
    if (i < n) deg[i] = 1.0f / fmaxf(deg[i], 1.0f);
}

// one warp per edge: gather 128 floats from src row, vector-reduce into dst row
__global__ void scatter_kernel(const float* __restrict__ h, const int* __restrict__ src,
                               const int* __restrict__ dst, float* __restrict__ agg, int E)
{
    int gt   = blockIdx.x * blockDim.x + threadIdx.x;
    int e    = gt >> 5;
    int lane = threadIdx.x & 31;
    if (e >= E) return;
    int s = __ldg(src + e);
    int d = __ldg(dst + e);
    float4 v = reinterpret_cast<const float4*>(h + (size_t)s * FD)[lane];
    float* p = agg + (size_t)d * FD + lane * 4;
    asm volatile("red.global.add.v4.f32 [%0], {%1, %2, %3, %4};"
                 :: "l"(p), "f"(v.x), "f"(v.y), "f"(v.z), "f"(v.w) : "memory");
}

// out[i] = base[i] + agg[i] * invdeg[node]
__global__ void combine_kernel(const float* __restrict__ base, const float* __restrict__ agg,
                               const float* __restrict__ invd, float* __restrict__ out, int N)
{
    int idx = blockIdx.x * blockDim.x + threadIdx.x;   // over N*32 float4s
    if (idx >= N * 32) return;
    int node = idx >> 5;
    float s  = invd[node];
    float4 b = reinterpret_cast<const float4*>(base)[idx];
    float4 a = reinterpret_cast<const float4*>(agg)[idx];
    reinterpret_cast<float4*>(out)[idx] =
        make_float4(b.x + a.x * s, b.y + a.y * s, b.z + a.z * s, b.w + a.w * s);
}

// ---------------- launch -----------------------------------------------------
extern "C" void kernel_launch(void* const* d_in, const int* in_sizes, int n_in,
                              void* d_out, int out_size)
{
    const float* x   = (const float*)d_in[0];
    const int*   src = (const int*)  d_in[1];
    const int*   dst = (const int*)  d_in[2];
    const float* W1  = (const float*)d_in[3];
    const float* b1  = (const float*)d_in[4];
    const float* W2  = (const float*)d_in[5];
    const float* b2  = (const float*)d_in[6];
    const float* W3  = (const float*)d_in[7];
    const float* b3  = (const float*)d_in[8];
    const float* Wo1 = (const float*)d_in[9];
    const float* bo1 = (const float*)d_in[10];
    const float* Wo2 = (const float*)d_in[11];
    const float* bo2 = (const float*)d_in[12];
    float* out = (float*)d_out;

    const int N = in_sizes[0] / FD;    // 100000
    const int E = in_sizes[1];         // 800000

    float *bufA, *bufB, *agg, *invd;
    cudaGetSymbolAddress((void**)&bufA, g_bufA);
    cudaGetSymbolAddress((void**)&bufB, g_bufB);
    cudaGetSymbolAddress((void**)&agg,  g_agg);
    cudaGetSymbolAddress((void**)&invd, g_invdeg);

    const int smem128 = (128 + 128) * 132 * (int)sizeof(float);  // 135168
    const int smem64  = (128 + 64)  * 132 * (int)sizeof(float);  // 101376
    cudaFuncSetAttribute(gemm_mma<128, true >, cudaFuncAttributeMaxDynamicSharedMemorySize, smem128);
    cudaFuncSetAttribute(gemm_mma<128, false>, cudaFuncAttributeMaxDynamicSharedMemorySize, smem128);
    cudaFuncSetAttribute(gemm_mma<64,  false>, cudaFuncAttributeMaxDynamicSharedMemorySize, smem64);

    const int gb = (N + 127) / 128;               // 782 row blocks
    const int zg = (N * 32 + 255) / 256;
    const int sg = (E * 32 + 255) / 256;

    // degrees (dst-only; recomputed each call for determinism)
    zero_kernel<<<(N / 4 + 255) / 256, 256>>>((float4*)invd, N / 4);
    deg_kernel<<<(E + 255) / 256, 256>>>(dst, E, invd);
    invdeg_kernel<<<(N + 255) / 256, 256>>>(invd, N);

    // x2 = lin(relu(lin(x,W1,b1)),W2,b2)
    gemm_mma<128, true ><<<gb, 256, smem128>>>(x,    W1, b1, bufA, N);
    gemm_mma<128, false><<<gb, 256, smem128>>>(bufA, W2, b2, bufB, N);

    // h = x2 + mean_agg(x2)
    zero_kernel<<<zg, 256>>>((float4*)agg, N * 32);
    scatter_kernel<<<sg, 256>>>(bufB, src, dst, agg, E);
    combine_kernel<<<zg, 256>>>(bufB, agg, invd, bufA, N);

    // h = lin(relu(lin(h,W1,b1)),W2,b2)   (g_agg reused as temp, re-zeroed later)
    gemm_mma<128, true ><<<gb, 256, smem128>>>(bufA, W1, b1, agg,  N);
    gemm_mma<128, false><<<gb, 256, smem128>>>(agg,  W2, b2, bufB, N);

    // h = relu(lin(h,W3,b3))
    gemm_mma<128, true ><<<gb, 256, smem128>>>(bufB, W3, b3, bufA, N);

    // h = h + mean_agg(h)
    zero_kernel<<<zg, 256>>>((float4*)agg, N * 32);
    scatter_kernel<<<sg, 256>>>(bufA, src, dst, agg, E);
    combine_kernel<<<zg, 256>>>(bufA, agg, invd, bufB, N);

    // h = relu(lin(h,W3,b3)); h = relu(lin(h,Wo1,bo1)); out = lin(h,Wo2,bo2)
    gemm_mma<128, true ><<<gb, 256, smem128>>>(bufB, W3,  b3,  bufA, N);
    gemm_mma<128, true ><<<gb, 256, smem128>>>(bufA, Wo1, bo1, bufB, N);
    gemm_mma<64,  false><<<gb, 256, smem64 >>>(bufB, Wo2, bo2, out,  N);
}

// round 4
// speedup vs baseline: 2.4510x; 1.1038x over previous
#include <cuda_runtime.h>
#include <cstdint>

#define NN 100000
#define EE 800000
#define FD 128

// ---------------- scratch (device globals; no allocations allowed) ----------
__device__ float g_bufA[NN * FD];
__device__ float g_bufB[NN * FD];
__device__ float g_agg [NN * FD];
__device__ float g_invdeg[NN];

// ---------------- tf32 split helpers -----------------------------------------
__device__ __forceinline__ void tf32_hilo(float x, uint32_t& h, uint32_t& l) {
    asm("cvt.rna.tf32.f32 %0, %1;" : "=r"(h) : "f"(x));
    float r = x - __uint_as_float(h);       // exact in fp32
    asm("cvt.rna.tf32.f32 %0, %1;" : "=r"(l) : "f"(r));
}

#define MMA_TF32(d, a, b)                                                     \
    asm volatile(                                                             \
        "mma.sync.aligned.m16n8k8.row.col.f32.tf32.tf32.f32 "                 \
        "{%0,%1,%2,%3}, {%4,%5,%6,%7}, {%8,%9}, {%0,%1,%2,%3};"               \
        : "+f"((d)[0]), "+f"((d)[1]), "+f"((d)[2]), "+f"((d)[3])              \
        : "r"((a)[0]), "r"((a)[1]), "r"((a)[2]), "r"((a)[3]),                 \
          "r"((b)[0]), "r"((b)[1]))

// ---------------- split-TF32 mma.sync GEMM ------------------------------------
// out[i][j] = act( sum_k in[i][k] * W[j][k] + b[j] )
// CTA: 512 threads = 16 warps (4 m x 4 n). Tile: 128 rows x NOUT cols, K=128.
// W split to tf32 hi/lo once at staging; A split in-loop (once per k-step).
// Per k-step: acc += Ah*Bh + Ah*Bl + Al*Bh   (lo*lo dropped, ~2^-22).
template<int NOUT, bool RELU>
__global__ void __launch_bounds__(512, 1)
gemm_mma(const float* __restrict__ A, const float* __restrict__ W,
         const float* __restrict__ bias, float* __restrict__ out, int N)
{
    constexpr int LDA = 132;              // padded stride: conflict-free, 16B-aligned
    constexpr int NC  = NOUT / 4;         // cols per n-warp: 32 or 16
    constexpr int NI  = NC / 8;           // n-frags per warp: 4 or 2
    extern __shared__ float sm[];
    float*    As = sm;                                    // [128][LDA] fp32
    uint32_t* Bh = reinterpret_cast<uint32_t*>(sm + 128 * LDA);   // [NOUT][LDA] tf32-hi
    uint32_t* Bl = Bh + NOUT * LDA;                                // [NOUT][LDA] tf32-lo

    const int tid  = threadIdx.x;
    const int wid  = tid >> 5;
    const int lane = tid & 31;
    const int wm   = wid & 3;              // warp row 0..3  (32 rows each)
    const int wn   = wid >> 2;             // warp col 0..3  (NC cols each)
    const int row0 = blockIdx.x * 128;
    const int qr   = lane >> 2;            // 0..7
    const int qc   = lane & 3;             // 0..3

    // ---- stage A tile (coalesced float4, zero-fill OOB rows) ----
    #pragma unroll
    for (int it = 0; it < 8; ++it) {
        int idx = tid + it * 512;
        int r = idx >> 5, c4 = idx & 31;
        int row = row0 + r;
        float4 v = make_float4(0.f, 0.f, 0.f, 0.f);
        if (row < N) v = reinterpret_cast<const float4*>(A)[(size_t)row * 32 + c4];
        *reinterpret_cast<float4*>(As + r * LDA + c4 * 4) = v;
    }
    // ---- stage W tile, splitting to tf32 hi/lo once ----
    #pragma unroll
    for (int it = 0; it < NOUT / 16; ++it) {
        int idx = tid + it * 512;
        int r = idx >> 5, c4 = idx & 31;
        float4 v = reinterpret_cast<const float4*>(W)[(size_t)r * 32 + c4];
        uint4 h, l;
        tf32_hilo(v.x, h.x, l.x); tf32_hilo(v.y, h.y, l.y);
        tf32_hilo(v.z, h.z, l.z); tf32_hilo(v.w, h.w, l.w);
        *reinterpret_cast<uint4*>(Bh + r * LDA + c4 * 4) = h;
        *reinterpret_cast<uint4*>(Bl + r * LDA + c4 * 4) = l;
    }
    __syncthreads();

    float acc[2][NI][4];
    #pragma unroll
    for (int mi = 0; mi < 2; ++mi)
        #pragma unroll
        for (int ni = 0; ni < NI; ++ni)
            #pragma unroll
            for (int c = 0; c < 4; ++c) acc[mi][ni][c] = 0.f;

    const float*    Ab  = As + (wm * 32 + qr) * LDA + qc;
    const uint32_t* Bhb = Bh + (wn * NC + qr) * LDA + qc;
    const uint32_t* Blb = Bl + (wn * NC + qr) * LDA + qc;

    #pragma unroll 2
    for (int ks = 0; ks < 16; ++ks) {
        const int k0 = ks * 8;
        uint32_t ah[2][4], al[2][4];
        #pragma unroll
        for (int mi = 0; mi < 2; ++mi) {
            const float* ap = Ab + mi * 16 * LDA + k0;
            tf32_hilo(ap[0],           ah[mi][0], al[mi][0]);
            tf32_hilo(ap[8 * LDA],     ah[mi][1], al[mi][1]);
            tf32_hilo(ap[4],           ah[mi][2], al[mi][2]);
            tf32_hilo(ap[8 * LDA + 4], ah[mi][3], al[mi][3]);
        }
        uint32_t bh[NI][2], bl[NI][2];
        #pragma unroll
        for (int ni = 0; ni < NI; ++ni) {
            const uint32_t* bp = Bhb + ni * 8 * LDA + k0;
            const uint32_t* lp = Blb + ni * 8 * LDA + k0;
            bh[ni][0] = bp[0]; bh[ni][1] = bp[4];
            bl[ni][0] = lp[0]; bl[ni][1] = lp[4];
        }
        #pragma unroll
        for (int mi = 0; mi < 2; ++mi)
            #pragma unroll
            for (int ni = 0; ni < NI; ++ni)
                MMA_TF32(acc[mi][ni], ah[mi], bh[ni]);
        #pragma unroll
        for (int mi = 0; mi < 2; ++mi)
            #pragma unroll
            for (int ni = 0; ni < NI; ++ni)
                MMA_TF32(acc[mi][ni], ah[mi], bl[ni]);
        #pragma unroll
        for (int mi = 0; mi < 2; ++mi)
            #pragma unroll
            for (int ni = 0; ni < NI; ++ni)
                MMA_TF32(acc[mi][ni], al[mi], bh[ni]);
    }

    // ---- epilogue: bias + act, direct float2 stores ----
    const int rbase = row0 + wm * 32 + qr;
    const int cbase = wn * NC + qc * 2;
    #pragma unroll
    for (int ni = 0; ni < NI; ++ni) {
        int c = cbase + ni * 8;
        float b0 = __ldg(bias + c), b1 = __ldg(bias + c + 1);
        #pragma unroll
        for (int mi = 0; mi < 2; ++mi) {
            int r = rbase + mi * 16;
            float v0 = acc[mi][ni][0] + b0;
            float v1 = acc[mi][ni][1] + b1;
            float v2 = acc[mi][ni][2] + b0;
            float v3 = acc[mi][ni][3] + b1;
            if (RELU) {
                v0 = fmaxf(v0, 0.f); v1 = fmaxf(v1, 0.f);
                v2 = fmaxf(v2, 0.f); v3 = fmaxf(v3, 0.f);
            }
            if (r < N)
                *reinterpret_cast<float2*>(out + (size_t)r * NOUT + c) = make_float2(v0, v1);
            if (r + 8 < N)
                *reinterpret_cast<float2*>(out + (size_t)(r + 8) * NOUT + c) = make_float2(v2, v3);
        }
    }
}

// ---------------- aggregation helpers ---------------------------------------
__global__ void zero_kernel(float4* p, int n4) {
    int i = blockIdx.x * blockDim.x + threadIdx.x;
    if (i < n4) p[i] = make_float4(0.f, 0.f, 0.f, 0.f);
}

__global__ void deg_kernel(const int* __restrict__ dst, int E, float* __restrict__ deg) {
    int i = blockIdx.x * blockDim.x + threadIdx.x;
    if (i < E) atomicAdd(&deg[dst[i]], 1.0f);
}

__global__ void invdeg_kernel(float* deg, int n) {
    int i = blockIdx.x * blockDim.x + threadIdx.x;
    if (i < n) deg[i] = 1.0f / fmaxf(deg[i], 1.0f);
}

// one warp per edge: gather 128 floats from src row, vector-reduce into dst row
__global__ void scatter_kernel(const float* __restrict__ h, const int* __restrict__ src,
                               const int* __restrict__ dst, float* __restrict__ agg, int E)
{
    int gt   = blockIdx.x * blockDim.x + threadIdx.x;
    int e    = gt >> 5;
    int lane = threadIdx.x & 31;
    if (e >= E) return;
    int s = __ldg(src + e);
    int d = __ldg(dst + e);
    float4 v = reinterpret_cast<const float4*>(h + (size_t)s * FD)[lane];
    float* p = agg + (size_t)d * FD + lane * 4;
    asm volatile("red.global.add.v4.f32 [%0], {%1, %2, %3, %4};"
                 :: "l"(p), "f"(v.x), "f"(v.y), "f"(v.z), "f"(v.w) : "memory");
}

// out[i] = base[i] + agg[i] * invdeg[node]
__global__ void combine_kernel(const float* __restrict__ base, const float* __restrict__ agg,
                               const float* __restrict__ invd, float* __restrict__ out, int N)
{
    int idx = blockIdx.x * blockDim.x + threadIdx.x;   // over N*32 float4s
    if (idx >= N * 32) return;
    int node = idx >> 5;
    float s  = invd[node];
    float4 b = reinterpret_cast<const float4*>(base)[idx];
    float4 a = reinterpret_cast<const float4*>(agg)[idx];
    reinterpret_cast<float4*>(out)[idx] =
        make_float4(b.x + a.x * s, b.y + a.y * s, b.z + a.z * s, b.w + a.w * s);
}

// ---------------- launch -----------------------------------------------------
extern "C" void kernel_launch(void* const* d_in, const int* in_sizes, int n_in,
                              void* d_out, int out_size)
{
    const float* x   = (const float*)d_in[0];
    const int*   src = (const int*)  d_in[1];
    const int*   dst = (const int*)  d_in[2];
    const float* W1  = (const float*)d_in[3];
    const float* b1  = (const float*)d_in[4];
    const float* W2  = (const float*)d_in[5];
    const float* b2  = (const float*)d_in[6];
    const float* W3  = (const float*)d_in[7];
    const float* b3  = (const float*)d_in[8];
    const float* Wo1 = (const float*)d_in[9];
    const float* bo1 = (const float*)d_in[10];
    const float* Wo2 = (const float*)d_in[11];
    const float* bo2 = (const float*)d_in[12];
    float* out = (float*)d_out;

    const int N = in_sizes[0] / FD;    // 100000
    const int E = in_sizes[1];         // 800000

    float *bufA, *bufB, *agg, *invd;
    cudaGetSymbolAddress((void**)&bufA, g_bufA);
    cudaGetSymbolAddress((void**)&bufB, g_bufB);
    cudaGetSymbolAddress((void**)&agg,  g_agg);
    cudaGetSymbolAddress((void**)&invd, g_invdeg);

    const int smem128 = (128 + 2 * 128) * 132 * (int)sizeof(float);  // 202752
    const int smem64  = (128 + 2 * 64)  * 132 * (int)sizeof(float);  // 135168
    cudaFuncSetAttribute(gemm_mma<128, true >, cudaFuncAttributeMaxDynamicSharedMemorySize, smem128);
    cudaFuncSetAttribute(gemm_mma<128, false>, cudaFuncAttributeMaxDynamicSharedMemorySize, smem128);
    cudaFuncSetAttribute(gemm_mma<64,  false>, cudaFuncAttributeMaxDynamicSharedMemorySize, smem64);

    const int gb = (N + 127) / 128;               // 782 row blocks
    const int zg = (N * 32 + 255) / 256;
    const int sg = (E * 32 + 255) / 256;

    // degrees (dst-only; recomputed each call for determinism)
    zero_kernel<<<(N / 4 + 255) / 256, 256>>>((float4*)invd, N / 4);
    deg_kernel<<<(E + 255) / 256, 256>>>(dst, E, invd);
    invdeg_kernel<<<(N + 255) / 256, 256>>>(invd, N);

    // x2 = lin(relu(lin(x,W1,b1)),W2,b2)
    gemm_mma<128, true ><<<gb, 512, smem128>>>(x,    W1, b1, bufA, N);
    gemm_mma<128, false><<<gb, 512, smem128>>>(bufA, W2, b2, bufB, N);

    // h = x2 + mean_agg(x2)
    zero_kernel<<<zg, 256>>>((float4*)agg, N * 32);
    scatter_kernel<<<sg, 256>>>(bufB, src, dst, agg, E);
    combine_kernel<<<zg, 256>>>(bufB, agg, invd, bufA, N);

    // h = lin(relu(lin(h,W1,b1)),W2,b2)   (g_agg reused as temp, re-zeroed later)
    gemm_mma<128, true ><<<gb, 512, smem128>>>(bufA, W1, b1, agg,  N);
    gemm_mma<128, false><<<gb, 512, smem128>>>(agg,  W2, b2, bufB, N);

    // h = relu(lin(h,W3,b3))
    gemm_mma<128, true ><<<gb, 512, smem128>>>(bufB, W3, b3, bufA, N);

    // h = h + mean_agg(h)
    zero_kernel<<<zg, 256>>>((float4*)agg, N * 32);
    scatter_kernel<<<sg, 256>>>(bufA, src, dst, agg, E);
    combine_kernel<<<zg, 256>>>(bufA, agg, invd, bufB, N);

    // h = relu(lin(h,W3,b3)); h = relu(lin(h,Wo1,bo1)); out = lin(h,Wo2,bo2)
    gemm_mma<128, true ><<<gb, 512, smem128>>>(bufB, W3,  b3,  bufA, N);
    gemm_mma<128, true ><<<gb, 512, smem128>>>(bufA, Wo1, bo1, bufB, N);
    gemm_mma<64,  false><<<gb, 512, smem64 >>>(bufB, Wo2, bo2, out,  N);
}

// round 5
// speedup vs baseline: 3.0209x; 1.2325x over previous
#include <cuda_runtime.h>
#include <cstdint>

#define NN 100000
#define EE 800000
#define FD 128

// ---------------- scratch (device globals; no allocations allowed) ----------
__device__ float g_bufA[NN * FD];
__device__ float g_bufB[NN * FD];
__device__ float g_bufC[NN * FD];
__device__ float g_invdeg[NN];
__device__ int   g_deg[NN];
__device__ int   g_off[NN + 1];
__device__ int   g_cnt[NN];
__device__ int   g_bsum[128];
__device__ int   g_csrc[EE];

// ---------------- helpers ----------------------------------------------------
__device__ __forceinline__ void tf32_hilo_cvt(float x, uint32_t& h, uint32_t& l) {
    asm("cvt.rna.tf32.f32 %0, %1;" : "=r"(h) : "f"(x));
    float r = x - __uint_as_float(h);
    asm("cvt.rna.tf32.f32 %0, %1;" : "=r"(l) : "f"(r));
}

#define LDSM4(q, addr)                                                        \
    asm volatile("ldmatrix.sync.aligned.m8n8.x4.shared.b16 {%0,%1,%2,%3}, [%4];" \
        : "=r"((q)[0]), "=r"((q)[1]), "=r"((q)[2]), "=r"((q)[3]) : "r"(addr))

// A fragment order from ldmatrix: {q0, q2, q1, q3}
#define MMA_TF32(d, a, b0, b1)                                                \
    asm volatile(                                                             \
        "mma.sync.aligned.m16n8k8.row.col.f32.tf32.tf32.f32 "                 \
        "{%0,%1,%2,%3}, {%4,%5,%6,%7}, {%8,%9}, {%0,%1,%2,%3};"               \
        : "+f"((d)[0]), "+f"((d)[1]), "+f"((d)[2]), "+f"((d)[3])              \
        : "r"((a)[0]), "r"((a)[2]), "r"((a)[1]), "r"((a)[3]),                 \
          "r"(b0), "r"(b1))

// ---------------- split-TF32 mma.sync GEMM ------------------------------------
// out[i][j] = act( sum_k in[i][k] * W[j][k] + b[j] )
// CTA: 512 threads = 16 warps (4m x 4n). Tile 128 x NOUT, K=128 single pass.
// W split to tf32 hi/lo at staging (cvt.rna). A split in-loop via mask:
//   ah = raw & 0xFFFFE000 (exact trunc), al = x - ah (HW truncates to tf32).
// acc += Ah*Bh + Ah*Bl + Al*Bh.
template<int NOUT, bool RELU>
__global__ void __launch_bounds__(512, 1)
gemm_mma(const float* __restrict__ A, const float* __restrict__ W,
         const float* __restrict__ bias, float* __restrict__ out, int N)
{
    constexpr int LDA = 140;              // 560B rows: ldmatrix conflict-free
    constexpr int NC  = NOUT / 4;         // cols per n-warp: 32 or 16
    constexpr int NI  = NC / 8;           // n-frags per warp: 4 or 2
    extern __shared__ float sm[];
    float*    As = sm;                                             // [128][LDA]
    uint32_t* Bh = reinterpret_cast<uint32_t*>(sm + 128 * LDA);    // [NOUT][LDA]
    uint32_t* Bl = Bh + NOUT * LDA;                                // [NOUT][LDA]

    const int tid  = threadIdx.x;
    const int wid  = tid >> 5;
    const int lane = tid & 31;
    const int wm   = wid & 3;
    const int wn   = wid >> 2;
    const int row0 = blockIdx.x * 128;
    const int qr   = lane >> 2;
    const int qc   = lane & 3;

    // ---- stage A tile (coalesced float4, zero-fill OOB rows) ----
    #pragma unroll
    for (int it = 0; it < 8; ++it) {
        int idx = tid + it * 512;
        int r = idx >> 5, c4 = idx & 31;
        int row = row0 + r;
        float4 v = make_float4(0.f, 0.f, 0.f, 0.f);
        if (row < N) v = reinterpret_cast<const float4*>(A)[(size_t)row * 32 + c4];
        *reinterpret_cast<float4*>(As + r * LDA + c4 * 4) = v;
    }
    // ---- stage W tile, split hi/lo once ----
    #pragma unroll
    for (int it = 0; it < NOUT / 16; ++it) {
        int idx = tid + it * 512;
        int r = idx >> 5, c4 = idx & 31;
        float4 v = reinterpret_cast<const float4*>(W)[(size_t)r * 32 + c4];
        uint4 h, l;
        tf32_hilo_cvt(v.x, h.x, l.x); tf32_hilo_cvt(v.y, h.y, l.y);
        tf32_hilo_cvt(v.z, h.z, l.z); tf32_hilo_cvt(v.w, h.w, l.w);
        *reinterpret_cast<uint4*>(Bh + r * LDA + c4 * 4) = h;
        *reinterpret_cast<uint4*>(Bl + r * LDA + c4 * 4) = l;
    }
    __syncthreads();

    float acc[2][NI][4];
    #pragma unroll
    for (int mi = 0; mi < 2; ++mi)
        #pragma unroll
        for (int ni = 0; ni < NI; ++ni)
            #pragma unroll
            for (int c = 0; c < 4; ++c) acc[mi][ni][c] = 0.f;

    // ldmatrix lane-constant bases
    uint32_t sb;
    asm("{ .reg .u64 t; cvta.to.shared.u64 t, %1; cvt.u32.u64 %0, t; }" : "=r"(sb) : "l"(sm));
    const uint32_t sBh = sb + 128u * LDA * 4u;
    const int m  = lane >> 3;
    const int mr = ((m >> 1) << 3) + (lane & 7);   // row within 16-row group
    const uint32_t mc = (uint32_t)(m & 1) * 16u;
    const uint32_t aBase0 = sb  + (uint32_t)(wm * 32 + mr) * (LDA * 4u) + mc;
    const uint32_t aBase1 = aBase0 + 16u * (LDA * 4u);
    const uint32_t bBase0 = sBh + (uint32_t)(wn * NC + mr) * (LDA * 4u) + mc;
    const uint32_t bBase1 = bBase0 + 16u * (LDA * 4u);
    const uint32_t BLOFS  = (uint32_t)NOUT * LDA * 4u;

    #pragma unroll 2
    for (int ks = 0; ks < 16; ++ks) {
        const uint32_t ko = (uint32_t)ks * 32u;

        uint32_t a0[4], a1[4], bh0[4], bl0[4], bh1[4], bl1[4];
        LDSM4(a0, aBase0 + ko);
        LDSM4(a1, aBase1 + ko);
        LDSM4(bh0, bBase0 + ko);
        LDSM4(bl0, bBase0 + BLOFS + ko);
        if (NI == 4) {
            LDSM4(bh1, bBase1 + ko);
            LDSM4(bl1, bBase1 + BLOFS + ko);
        }

        uint32_t ah[2][4], al[2][4];
        #pragma unroll
        for (int j = 0; j < 4; ++j) {
            ah[0][j] = a0[j] & 0xFFFFE000u;
            ah[1][j] = a1[j] & 0xFFFFE000u;
            al[0][j] = __float_as_uint(__uint_as_float(a0[j]) - __uint_as_float(ah[0][j]));
            al[1][j] = __float_as_uint(__uint_as_float(a1[j]) - __uint_as_float(ah[1][j]));
        }

        #pragma unroll
        for (int mi = 0; mi < 2; ++mi) {
            MMA_TF32(acc[mi][0], ah[mi], bh0[0], bh0[1]);
            MMA_TF32(acc[mi][1], ah[mi], bh0[2], bh0[3]);
            if (NI == 4) {
                MMA_TF32(acc[mi][2], ah[mi], bh1[0], bh1[1]);
                MMA_TF32(acc[mi][3], ah[mi], bh1[2], bh1[3]);
            }
        }
        #pragma unroll
        for (int mi = 0; mi < 2; ++mi) {
            MMA_TF32(acc[mi][0], ah[mi], bl0[0], bl0[1]);
            MMA_TF32(acc[mi][1], ah[mi], bl0[2], bl0[3]);
            if (NI == 4) {
                MMA_TF32(acc[mi][2], ah[mi], bl1[0], bl1[1]);
                MMA_TF32(acc[mi][3], ah[mi], bl1[2], bl1[3]);
            }
        }
        #pragma unroll
        for (int mi = 0; mi < 2; ++mi) {
            MMA_TF32(acc[mi][0], al[mi], bh0[0], bh0[1]);
            MMA_TF32(acc[mi][1], al[mi], bh0[2], bh0[3]);
            if (NI == 4) {
                MMA_TF32(acc[mi][2], al[mi], bh1[0], bh1[1]);
                MMA_TF32(acc[mi][3], al[mi], bh1[2], bh1[3]);
            }
        }
    }

    // ---- epilogue: bias + act, float2 stores ----
    const int rbase = row0 + wm * 32 + qr;
    const int cbase = wn * NC + qc * 2;
    #pragma unroll
    for (int ni = 0; ni < NI; ++ni) {
        int c = cbase + ni * 8;
        float b0 = __ldg(bias + c), b1 = __ldg(bias + c + 1);
        #pragma unroll
        for (int mi = 0; mi < 2; ++mi) {
            int r = rbase + mi * 16;
            float v0 = acc[mi][ni][0] + b0;
            float v1 = acc[mi][ni][1] + b1;
            float v2 = acc[mi][ni][2] + b0;
            float v3 = acc[mi][ni][3] + b1;
            if (RELU) {
                v0 = fmaxf(v0, 0.f); v1 = fmaxf(v1, 0.f);
                v2 = fmaxf(v2, 0.f); v3 = fmaxf(v3, 0.f);
            }
            if (r < N)
                *reinterpret_cast<float2*>(out + (size_t)r * NOUT + c) = make_float2(v0, v1);
            if (r + 8 < N)
                *reinterpret_cast<float2*>(out + (size_t)(r + 8) * NOUT + c) = make_float2(v2, v3);
        }
    }
}

// ---------------- CSR build ---------------------------------------------------
__global__ void zero_int_kernel(int* p, int n) {
    int i = blockIdx.x * blockDim.x + threadIdx.x;
    if (i < n) p[i] = 0;
}
__global__ void hist_kernel(const int* __restrict__ dst, int E, int* __restrict__ deg) {
    int i = blockIdx.x * blockDim.x + threadIdx.x;
    if (i < E) atomicAdd(&deg[dst[i]], 1);
}
__global__ void csr_scan1(const int* __restrict__ deg, int* __restrict__ off,
                          int* __restrict__ bsum, float* __restrict__ invd,
                          int* __restrict__ cnt, int n) {
    __shared__ int s[1024];
    int g = blockIdx.x * 1024 + threadIdx.x;
    int v = (g < n) ? deg[g] : 0;
    if (g < n) { invd[g] = 1.0f / fmaxf((float)v, 1.0f); cnt[g] = 0; }
    s[threadIdx.x] = v;
    __syncthreads();
    #pragma unroll
    for (int d = 1; d < 1024; d <<= 1) {
        int t = (threadIdx.x >= d) ? s[threadIdx.x - d] : 0;
        __syncthreads();
        s[threadIdx.x] += t;
        __syncthreads();
    }
    if (g < n) off[g + 1] = s[threadIdx.x];
    if (threadIdx.x == 1023) bsum[blockIdx.x] = s[1023];
}
__global__ void csr_scan2(int* bsum, int nb) {
    if (threadIdx.x == 0) {
        int acc = 0;
        for (int i = 0; i < nb; ++i) { int v = bsum[i]; bsum[i] = acc; acc += v; }
    }
}
__global__ void csr_scan3(int* __restrict__ off, const int* __restrict__ bsum, int n) {
    int g = blockIdx.x * 1024 + threadIdx.x;
    if (g < n) off[g + 1] += bsum[blockIdx.x];
    if (g == 0) off[0] = 0;
}
__global__ void csr_fill(const int* __restrict__ src, const int* __restrict__ dst,
                         const int* __restrict__ off, int* __restrict__ cnt,
                         int* __restrict__ csrc, int E) {
    int i = blockIdx.x * blockDim.x + threadIdx.x;
    if (i < E) {
        int d = dst[i];
        int p = off[d] + atomicAdd(&cnt[d], 1);
        csrc[p] = src[i];
    }
}

// ---------------- fused mean-aggregate: out = h + mean_in(h) ------------------
// one warp per node, gather incoming src rows via CSR
__global__ void aggregate_kernel(const float* __restrict__ h, const int* __restrict__ off,
                                 const int* __restrict__ csrc, const float* __restrict__ invd,
                                 float* __restrict__ out, int N)
{
    int wid  = threadIdx.x >> 5;
    int lane = threadIdx.x & 31;
    int node = blockIdx.x * (blockDim.x >> 5) + wid;
    if (node >= N) return;
    int beg = off[node], end = off[node + 1];
    float4 acc = make_float4(0.f, 0.f, 0.f, 0.f);
    const float4* h4 = reinterpret_cast<const float4*>(h);
    int e = beg;
    for (; e + 1 < end; e += 2) {
        int s0 = __ldg(csrc + e), s1 = __ldg(csrc + e + 1);
        float4 v0 = __ldg(h4 + s0 * 32 + lane);
        float4 v1 = __ldg(h4 + s1 * 32 + lane);
        acc.x += v0.x + v1.x; acc.y += v0.y + v1.y;
        acc.z += v0.z + v1.z; acc.w += v0.w + v1.w;
    }
    if (e < end) {
        int s0 = __ldg(csrc + e);
        float4 v0 = __ldg(h4 + s0 * 32 + lane);
        acc.x += v0.x; acc.y += v0.y; acc.z += v0.z; acc.w += v0.w;
    }
    float iv = invd[node];
    float4 b = __ldg(h4 + node * 32 + lane);
    reinterpret_cast<float4*>(out)[node * 32 + lane] =
        make_float4(b.x + acc.x * iv, b.y + acc.y * iv,
                    b.z + acc.z * iv, b.w + acc.w * iv);
}

// ---------------- launch -----------------------------------------------------
extern "C" void kernel_launch(void* const* d_in, const int* in_sizes, int n_in,
                              void* d_out, int out_size)
{
    const float* x   = (const float*)d_in[0];
    const int*   src = (const int*)  d_in[1];
    const int*   dst = (const int*)  d_in[2];
    const float* W1  = (const float*)d_in[3];
    const float* b1  = (const float*)d_in[4];
    const float* W2  = (const float*)d_in[5];
    const float* b2  = (const float*)d_in[6];
    const float* W3  = (const float*)d_in[7];
    const float* b3  = (const float*)d_in[8];
    const float* Wo1 = (const float*)d_in[9];
    const float* bo1 = (const float*)d_in[10];
    const float* Wo2 = (const float*)d_in[11];
    const float* bo2 = (const float*)d_in[12];
    float* out = (float*)d_out;

    const int N = in_sizes[0] / FD;    // 100000
    const int E = in_sizes[1];         // 800000

    float *bufA, *bufB, *bufC, *invd;
    int *deg, *off, *cnt, *bsum, *csrc;
    cudaGetSymbolAddress((void**)&bufA, g_bufA);
    cudaGetSymbolAddress((void**)&bufB, g_bufB);
    cudaGetSymbolAddress((void**)&bufC, g_bufC);
    cudaGetSymbolAddress((void**)&invd, g_invdeg);
    cudaGetSymbolAddress((void**)&deg,  g_deg);
    cudaGetSymbolAddress((void**)&off,  g_off);
    cudaGetSymbolAddress((void**)&cnt,  g_cnt);
    cudaGetSymbolAddress((void**)&bsum, g_bsum);
    cudaGetSymbolAddress((void**)&csrc, g_csrc);

    const int smem128 = 3 * 128 * 140 * (int)sizeof(float);             // 215040
    const int smem64  = (128 + 2 * 64) * 140 * (int)sizeof(float);      // 143360
    cudaFuncSetAttribute(gemm_mma<128, true >, cudaFuncAttributeMaxDynamicSharedMemorySize, smem128);
    cudaFuncSetAttribute(gemm_mma<128, false>, cudaFuncAttributeMaxDynamicSharedMemorySize, smem128);
    cudaFuncSetAttribute(gemm_mma<64,  false>, cudaFuncAttributeMaxDynamicSharedMemorySize, smem64);

    const int gb = (N + 127) / 128;               // 782 row blocks
    const int nb = (N + 1023) / 1024;             // 98 scan blocks
    const int ag = (N + 7) / 8;                   // aggregate: 8 warps/block

    // ---- CSR build (once per call; reused by both aggregations) ----
    zero_int_kernel<<<(N + 255) / 256, 256>>>(deg, N);
    hist_kernel<<<(E + 255) / 256, 256>>>(dst, E, deg);
    csr_scan1<<<nb, 1024>>>(deg, off, bsum, invd, cnt, N);
    csr_scan2<<<1, 32>>>(bsum, nb);
    csr_scan3<<<nb, 1024>>>(off, bsum, N);
    csr_fill<<<(E + 255) / 256, 256>>>(src, dst, off, cnt, csrc, E);

    // x2 = lin(relu(lin(x,W1,b1)),W2,b2)
    gemm_mma<128, true ><<<gb, 512, smem128>>>(x,    W1, b1, bufA, N);
    gemm_mma<128, false><<<gb, 512, smem128>>>(bufA, W2, b2, bufB, N);

    // h = x2 + mean_agg(x2)
    aggregate_kernel<<<ag, 256>>>(bufB, off, csrc, invd, bufA, N);

    // h = lin(relu(lin(h,W1,b1)),W2,b2)
    gemm_mma<128, true ><<<gb, 512, smem128>>>(bufA, W1, b1, bufC, N);
    gemm_mma<128, false><<<gb, 512, smem128>>>(bufC, W2, b2, bufB, N);

    // h = relu(lin(h,W3,b3))
    gemm_mma<128, true ><<<gb, 512, smem128>>>(bufB, W3, b3, bufA, N);

    // h = h + mean_agg(h)
    aggregate_kernel<<<ag, 256>>>(bufA, off, csrc, invd, bufB, N);

    // h = relu(lin(h,W3,b3)); h = relu(lin(h,Wo1,bo1)); out = lin(h,Wo2,bo2)
    gemm_mma<128, true ><<<gb, 512, smem128>>>(bufB, W3,  b3,  bufA, N);
    gemm_mma<128, true ><<<gb, 512, smem128>>>(bufA, Wo1, bo1, bufB, N);
    gemm_mma<64,  false><<<gb, 512, smem64 >>>(bufB, Wo2, bo2, out,  N);
}

// round 6
// speedup vs baseline: 3.5945x; 1.1899x over previous
#include <cuda_runtime.h>
#include <cstdint>

#define NN 100000
#define EE 800000
#define FD 128

// ---------------- scratch (device globals; no allocations allowed) ----------
__device__ float g_bufA[NN * FD];
__device__ float g_bufB[NN * FD];
__device__ float g_bufC[NN * FD];
__device__ float g_invdeg[NN];
__device__ int   g_deg[NN];
__device__ int   g_off[NN + 1];
__device__ int   g_cnt[NN];
__device__ int   g_bsum[128];
__device__ int   g_csrc[EE];

// ---------------- helpers ----------------------------------------------------
#define LDSM4(q, addr)                                                        \
    asm volatile("ldmatrix.sync.aligned.m8n8.x4.shared.b16 {%0,%1,%2,%3}, [%4];" \
        : "=r"((q)[0]), "=r"((q)[1]), "=r"((q)[2]), "=r"((q)[3]) : "r"(addr))

// A fragment order from ldmatrix: {q0, q2, q1, q3}
#define MMA_TF32(d, a, b0, b1)                                                \
    asm volatile(                                                             \
        "mma.sync.aligned.m16n8k8.row.col.f32.tf32.tf32.f32 "                 \
        "{%0,%1,%2,%3}, {%4,%5,%6,%7}, {%8,%9}, {%0,%1,%2,%3};"               \
        : "+f"((d)[0]), "+f"((d)[1]), "+f"((d)[2]), "+f"((d)[3])              \
        : "r"((a)[0]), "r"((a)[2]), "r"((a)[1]), "r"((a)[3]),                 \
          "r"(b0), "r"(b1))

#define SPLIT4(hi, lo, raw)                                                   \
    _Pragma("unroll")                                                         \
    for (int j = 0; j < 4; ++j) {                                             \
        (hi)[j] = (raw)[j] & 0xFFFFE000u;                                     \
        (lo)[j] = __float_as_uint(__uint_as_float((raw)[j]) -                 \
                                  __uint_as_float((hi)[j]));                  \
    }

// ---------------- split-TF32 mma.sync GEMM ------------------------------------
// out[i][j] = act( sum_k in[i][k] * W[j][k] + b[j] )
// CTA: 256 threads = 8 warps (2m x 4n). Tile 64 x NOUT, K=128 single pass.
// A and W stored raw fp32 in smem; mask-split to tf32 hi/lo in registers:
//   hi = raw & 0xFFFFE000 (exact trunc), lo = x - hi (HW truncates to tf32).
// acc += Ah*Bh + Ah*Bl + Al*Bh.  smem 107.5KB -> 2 CTAs/SM overlap.
template<int NOUT, bool RELU>
__global__ void __launch_bounds__(256, 2)
gemm_mma(const float* __restrict__ A, const float* __restrict__ W,
         const float* __restrict__ bias, float* __restrict__ out, int N)
{
    constexpr int LDA = 140;              // 560B rows: ldmatrix conflict-free
    constexpr int NC  = NOUT / 4;         // cols per n-warp: 32 or 16
    constexpr int NI  = NC / 8;           // n-frags per warp: 4 or 2
    extern __shared__ float sm[];
    float* As = sm;                        // [64][LDA] fp32
    float* Bs = sm + 64 * LDA;             // [NOUT][LDA] fp32

    const int tid  = threadIdx.x;
    const int wid  = tid >> 5;
    const int lane = tid & 31;
    const int wm   = wid & 1;              // warp row 0..1 (32 rows each)
    const int wn   = wid >> 1;             // warp col 0..3 (NC cols each)
    const int row0 = blockIdx.x * 64;
    const int qr   = lane >> 2;
    const int qc   = lane & 3;

    // ---- stage A tile (coalesced float4, zero-fill OOB rows) ----
    #pragma unroll
    for (int it = 0; it < 8; ++it) {
        int idx = tid + it * 256;
        int r = idx >> 5, c4 = idx & 31;
        int row = row0 + r;
        float4 v = make_float4(0.f, 0.f, 0.f, 0.f);
        if (row < N) v = reinterpret_cast<const float4*>(A)[(size_t)row * 32 + c4];
        *reinterpret_cast<float4*>(As + r * LDA + c4 * 4) = v;
    }
    // ---- stage W tile raw ----
    #pragma unroll
    for (int it = 0; it < NOUT / 8; ++it) {
        int idx = tid + it * 256;
        int r = idx >> 5, c4 = idx & 31;
        float4 v = reinterpret_cast<const float4*>(W)[(size_t)r * 32 + c4];
        *reinterpret_cast<float4*>(Bs + r * LDA + c4 * 4) = v;
    }
    __syncthreads();

    float acc[2][NI][4];
    #pragma unroll
    for (int mi = 0; mi < 2; ++mi)
        #pragma unroll
        for (int ni = 0; ni < NI; ++ni)
            #pragma unroll
            for (int c = 0; c < 4; ++c) acc[mi][ni][c] = 0.f;

    // ldmatrix lane-constant bases
    uint32_t sb;
    asm("{ .reg .u64 t; cvta.to.shared.u64 t, %1; cvt.u32.u64 %0, t; }" : "=r"(sb) : "l"(sm));
    const uint32_t sB = sb + 64u * LDA * 4u;
    const int m  = lane >> 3;
    const int mr = ((m >> 1) << 3) + (lane & 7);   // row within 16-row group
    const uint32_t mc = (uint32_t)(m & 1) * 16u;
    const uint32_t aBase0 = sb + (uint32_t)(wm * 32 + mr) * (LDA * 4u) + mc;
    const uint32_t aBase1 = aBase0 + 16u * (LDA * 4u);
    const uint32_t bBase0 = sB + (uint32_t)(wn * NC + mr) * (LDA * 4u) + mc;
    const uint32_t bBase1 = bBase0 + 16u * (LDA * 4u);

    #pragma unroll 2
    for (int ks = 0; ks < 16; ++ks) {
        const uint32_t ko = (uint32_t)ks * 32u;

        uint32_t a0[4], a1[4], br0[4], br1[4];
        LDSM4(a0, aBase0 + ko);
        LDSM4(a1, aBase1 + ko);
        LDSM4(br0, bBase0 + ko);
        if (NI == 4) LDSM4(br1, bBase1 + ko);

        uint32_t ah[2][4], al[2][4];
        SPLIT4(ah[0], al[0], a0);
        SPLIT4(ah[1], al[1], a1);
        uint32_t bh0[4], bl0[4], bh1[4], bl1[4];
        SPLIT4(bh0, bl0, br0);
        if (NI == 4) SPLIT4(bh1, bl1, br1);

        #pragma unroll
        for (int mi = 0; mi < 2; ++mi) {
            MMA_TF32(acc[mi][0], ah[mi], bh0[0], bh0[1]);
            MMA_TF32(acc[mi][1], ah[mi], bh0[2], bh0[3]);
            if (NI == 4) {
                MMA_TF32(acc[mi][2], ah[mi], bh1[0], bh1[1]);
                MMA_TF32(acc[mi][3], ah[mi], bh1[2], bh1[3]);
            }
        }
        #pragma unroll
        for (int mi = 0; mi < 2; ++mi) {
            MMA_TF32(acc[mi][0], ah[mi], bl0[0], bl0[1]);
            MMA_TF32(acc[mi][1], ah[mi], bl0[2], bl0[3]);
            if (NI == 4) {
                MMA_TF32(acc[mi][2], ah[mi], bl1[0], bl1[1]);
                MMA_TF32(acc[mi][3], ah[mi], bl1[2], bl1[3]);
            }
        }
        #pragma unroll
        for (int mi = 0; mi < 2; ++mi) {
            MMA_TF32(acc[mi][0], al[mi], bh0[0], bh0[1]);
            MMA_TF32(acc[mi][1], al[mi], bh0[2], bh0[3]);
            if (NI == 4) {
                MMA_TF32(acc[mi][2], al[mi], bh1[0], bh1[1]);
                MMA_TF32(acc[mi][3], al[mi], bh1[2], bh1[3]);
            }
        }
    }

    // ---- epilogue: bias + act, float2 stores ----
    const int rbase = row0 + wm * 32 + qr;
    const int cbase = wn * NC + qc * 2;
    #pragma unroll
    for (int ni = 0; ni < NI; ++ni) {
        int c = cbase + ni * 8;
        float b0 = __ldg(bias + c), b1 = __ldg(bias + c + 1);
        #pragma unroll
        for (int mi = 0; mi < 2; ++mi) {
            int r = rbase + mi * 16;
            float v0 = acc[mi][ni][0] + b0;
            float v1 = acc[mi][ni][1] + b1;
            float v2 = acc[mi][ni][2] + b0;
            float v3 = acc[mi][ni][3] + b1;
            if (RELU) {
                v0 = fmaxf(v0, 0.f); v1 = fmaxf(v1, 0.f);
                v2 = fmaxf(v2, 0.f); v3 = fmaxf(v3, 0.f);
            }
            if (r < N)
                *reinterpret_cast<float2*>(out + (size_t)r * NOUT + c) = make_float2(v0, v1);
            if (r + 8 < N)
                *reinterpret_cast<float2*>(out + (size_t)(r + 8) * NOUT + c) = make_float2(v2, v3);
        }
    }
}

// ---------------- CSR build ---------------------------------------------------
__global__ void zero_int_kernel(int* p, int n) {
    int i = blockIdx.x * blockDim.x + threadIdx.x;
    if (i < n) p[i] = 0;
}
__global__ void hist_kernel(const int* __restrict__ dst, int E, int* __restrict__ deg) {
    int i = blockIdx.x * blockDim.x + threadIdx.x;
    if (i < E) atomicAdd(&deg[dst[i]], 1);
}
__global__ void csr_scan1(const int* __restrict__ deg, int* __restrict__ off,
                          int* __restrict__ bsum, float* __restrict__ invd,
                          int* __restrict__ cnt, int n) {
    __shared__ int s[1024];
    int g = blockIdx.x * 1024 + threadIdx.x;
    int v = (g < n) ? deg[g] : 0;
    if (g < n) { invd[g] = 1.0f / fmaxf((float)v, 1.0f); cnt[g] = 0; }
    s[threadIdx.x] = v;
    __syncthreads();
    #pragma unroll
    for (int d = 1; d < 1024; d <<= 1) {
        int t = (threadIdx.x >= d) ? s[threadIdx.x - d] : 0;
        __syncthreads();
        s[threadIdx.x] += t;
        __syncthreads();
    }
    if (g < n) off[g + 1] = s[threadIdx.x];
    if (threadIdx.x == 1023) bsum[blockIdx.x] = s[1023];
}
__global__ void csr_scan2(int* bsum, int nb) {
    __shared__ int s[128];
    int v = (threadIdx.x < nb) ? bsum[threadIdx.x] : 0;
    s[threadIdx.x] = v;
    __syncthreads();
    #pragma unroll
    for (int d = 1; d < 128; d <<= 1) {
        int t = (threadIdx.x >= d) ? s[threadIdx.x - d] : 0;
        __syncthreads();
        s[threadIdx.x] += t;
        __syncthreads();
    }
    if (threadIdx.x < nb) bsum[threadIdx.x] = s[threadIdx.x] - v;  // exclusive
}
__global__ void csr_scan3(int* __restrict__ off, const int* __restrict__ bsum, int n) {
    int g = blockIdx.x * 1024 + threadIdx.x;
    if (g < n) off[g + 1] += bsum[blockIdx.x];
    if (g == 0) off[0] = 0;
}
__global__ void csr_fill(const int* __restrict__ src, const int* __restrict__ dst,
                         const int* __restrict__ off, int* __restrict__ cnt,
                         int* __restrict__ csrc, int E) {
    int i = blockIdx.x * blockDim.x + threadIdx.x;
    if (i < E) {
        int d = dst[i];
        int p = off[d] + atomicAdd(&cnt[d], 1);
        csrc[p] = src[i];
    }
}

// ---------------- fused mean-aggregate: out = h + mean_in(h) ------------------
// one warp per node, gather incoming src rows via CSR
__global__ void aggregate_kernel(const float* __restrict__ h, const int* __restrict__ off,
                                 const int* __restrict__ csrc, const float* __restrict__ invd,
                                 float* __restrict__ out, int N)
{
    int wid  = threadIdx.x >> 5;
    int lane = threadIdx.x & 31;
    int node = blockIdx.x * (blockDim.x >> 5) + wid;
    if (node >= N) return;
    int beg = off[node], end = off[node + 1];
    float4 acc = make_float4(0.f, 0.f, 0.f, 0.f);
    const float4* h4 = reinterpret_cast<const float4*>(h);
    int e = beg;
    for (; e + 1 < end; e += 2) {
        int s0 = __ldg(csrc + e), s1 = __ldg(csrc + e + 1);
        float4 v0 = __ldg(h4 + s0 * 32 + lane);
        float4 v1 = __ldg(h4 + s1 * 32 + lane);
        acc.x += v0.x + v1.x; acc.y += v0.y + v1.y;
        acc.z += v0.z + v1.z; acc.w += v0.w + v1.w;
    }
    if (e < end) {
        int s0 = __ldg(csrc + e);
        float4 v0 = __ldg(h4 + s0 * 32 + lane);
        acc.x += v0.x; acc.y += v0.y; acc.z += v0.z; acc.w += v0.w;
    }
    float iv = invd[node];
    float4 b = __ldg(h4 + node * 32 + lane);
    reinterpret_cast<float4*>(out)[node * 32 + lane] =
        make_float4(b.x + acc.x * iv, b.y + acc.y * iv,
                    b.z + acc.z * iv, b.w + acc.w * iv);
}

// ---------------- launch -----------------------------------------------------
extern "C" void kernel_launch(void* const* d_in, const int* in_sizes, int n_in,
                              void* d_out, int out_size)
{
    const float* x   = (const float*)d_in[0];
    const int*   src = (const int*)  d_in[1];
    const int*   dst = (const int*)  d_in[2];
    const float* W1  = (const float*)d_in[3];
    const float* b1  = (const float*)d_in[4];
    const float* W2  = (const float*)d_in[5];
    const float* b2  = (const float*)d_in[6];
    const float* W3  = (const float*)d_in[7];
    const float* b3  = (const float*)d_in[8];
    const float* Wo1 = (const float*)d_in[9];
    const float* bo1 = (const float*)d_in[10];
    const float* Wo2 = (const float*)d_in[11];
    const float* bo2 = (const float*)d_in[12];
    float* out = (float*)d_out;

    const int N = in_sizes[0] / FD;    // 100000
    const int E = in_sizes[1];         // 800000

    float *bufA, *bufB, *bufC, *invd;
    int *deg, *off, *cnt, *bsum, *csrc;
    cudaGetSymbolAddress((void**)&bufA, g_bufA);
    cudaGetSymbolAddress((void**)&bufB, g_bufB);
    cudaGetSymbolAddress((void**)&bufC, g_bufC);
    cudaGetSymbolAddress((void**)&invd, g_invdeg);
    cudaGetSymbolAddress((void**)&deg,  g_deg);
    cudaGetSymbolAddress((void**)&off,  g_off);
    cudaGetSymbolAddress((void**)&cnt,  g_cnt);
    cudaGetSymbolAddress((void**)&bsum, g_bsum);
    cudaGetSymbolAddress((void**)&csrc, g_csrc);

    const int smem128 = (64 + 128) * 140 * (int)sizeof(float);  // 107520
    const int smem64  = (64 + 64)  * 140 * (int)sizeof(float);  // 71680
    cudaFuncSetAttribute(gemm_mma<128, true >, cudaFuncAttributeMaxDynamicSharedMemorySize, smem128);
    cudaFuncSetAttribute(gemm_mma<128, false>, cudaFuncAttributeMaxDynamicSharedMemorySize, smem128);
    cudaFuncSetAttribute(gemm_mma<64,  false>, cudaFuncAttributeMaxDynamicSharedMemorySize, smem64);

    const int gb = (N + 63) / 64;                 // 1563 row blocks
    const int nb = (N + 1023) / 1024;             // 98 scan blocks
    const int ag = (N + 7) / 8;                   // aggregate: 8 warps/block

    // ---- CSR build (once per call; reused by both aggregations) ----
    zero_int_kernel<<<(N + 255) / 256, 256>>>(deg, N);
    hist_kernel<<<(E + 255) / 256, 256>>>(dst, E, deg);
    csr_scan1<<<nb, 1024>>>(deg, off, bsum, invd, cnt, N);
    csr_scan2<<<1, 128>>>(bsum, nb);
    csr_scan3<<<nb, 1024>>>(off, bsum, N);
    csr_fill<<<(E + 255) / 256, 256>>>(src, dst, off, cnt, csrc, E);

    // x2 = lin(relu(lin(x,W1,b1)),W2,b2)
    gemm_mma<128, true ><<<gb, 256, smem128>>>(x,    W1, b1, bufA, N);
    gemm_mma<128, false><<<gb, 256, smem128>>>(bufA, W2, b2, bufB, N);

    // h = x2 + mean_agg(x2)
    aggregate_kernel<<<ag, 256>>>(bufB, off, csrc, invd, bufA, N);

    // h = lin(relu(lin(h,W1,b1)),W2,b2)
    gemm_mma<128, true ><<<gb, 256, smem128>>>(bufA, W1, b1, bufC, N);
    gemm_mma<128, false><<<gb, 256, smem128>>>(bufC, W2, b2, bufB, N);

    // h = relu(lin(h,W3,b3))
    gemm_mma<128, true ><<<gb, 256, smem128>>>(bufB, W3, b3, bufA, N);

    // h = h + mean_agg(h)
    aggregate_kernel<<<ag, 256>>>(bufA, off, csrc, invd, bufB, N);

    // h = relu(lin(h,W3,b3)); h = relu(lin(h,Wo1,bo1)); out = lin(h,Wo2,bo2)
    gemm_mma<128, true ><<<gb, 256, smem128>>>(bufB, W3,  b3,  bufA, N);
    gemm_mma<128, true ><<<gb, 256, smem128>>>(bufA, Wo1, bo1, bufB, N);
    gemm_mma<64,  false><<<gb, 256, smem64 >>>(bufB, Wo2, bo2, out,  N);
}

// round 7
// speedup vs baseline: 3.7708x; 1.0490x over previous
#include <cuda_runtime.h>
#include <cstdint>

#define NN 100000
#define EE 800000
#define FD 128

// ---------------- scratch (device globals; no allocations allowed) ----------
__device__ float g_bufA[NN * FD];
__device__ float g_bufB[NN * FD];
__device__ float g_bufC[NN * FD];
__device__ float g_invdeg[NN];
__device__ int   g_deg[NN];
__device__ int   g_off[NN + 1];
__device__ int   g_cnt[NN];
__device__ int   g_bsum[128];
__device__ int   g_csrc[EE];

// ---------------- helpers ----------------------------------------------------
#define LDSM4(q, addr)                                                        \
    asm volatile("ldmatrix.sync.aligned.m8n8.x4.shared.b16 {%0,%1,%2,%3}, [%4];" \
        : "=r"((q)[0]), "=r"((q)[1]), "=r"((q)[2]), "=r"((q)[3]) : "r"(addr))

// A fragment order from ldmatrix: {q0, q2, q1, q3}
#define MMA_TF32(d, a, b0, b1)                                                \
    asm volatile(                                                             \
        "mma.sync.aligned.m16n8k8.row.col.f32.tf32.tf32.f32 "                 \
        "{%0,%1,%2,%3}, {%4,%5,%6,%7}, {%8,%9}, {%0,%1,%2,%3};"               \
        : "+f"((d)[0]), "+f"((d)[1]), "+f"((d)[2]), "+f"((d)[3])              \
        : "r"((a)[0]), "r"((a)[2]), "r"((a)[1]), "r"((a)[3]),                 \
          "r"(b0), "r"(b1))

#define SPLIT4(hi, lo, raw)                                                   \
    _Pragma("unroll")                                                         \
    for (int j = 0; j < 4; ++j) {                                             \
        (hi)[j] = (raw)[j] & 0xFFFFE000u;                                     \
        (lo)[j] = __float_as_uint(__uint_as_float((raw)[j]) -                 \
                                  __uint_as_float((hi)[j]));                  \
    }

// ---------------- split-TF32 mma.sync GEMM ------------------------------------
// out[i][j] = act( sum_k in[i][k] * W[j][k] + b[j] )
// CTA: 256 threads = 8 warps (2m x 4n). Tile 64 x NOUT, K=128 single pass.
// A and W raw fp32 in smem; mask-split to tf32 hi/lo in registers.
// acc += Ah*Bh + Ah*Bl + Al*Bh.  smem 107.5KB -> 2 CTAs/SM.
// k-loop software-pipelined: LDSM for ks+1 issued before MMAs of ks.
template<int NOUT, bool RELU>
__global__ void __launch_bounds__(256, 2)
gemm_mma(const float* __restrict__ A, const float* __restrict__ W,
         const float* __restrict__ bias, float* __restrict__ out, int N)
{
    constexpr int LDA = 140;              // 560B rows: ldmatrix conflict-free
    constexpr int NC  = NOUT / 4;         // cols per n-warp: 32 or 16
    constexpr int NI  = NC / 8;           // n-frags per warp: 4 or 2
    extern __shared__ float sm[];
    float* As = sm;                        // [64][LDA] fp32
    float* Bs = sm + 64 * LDA;             // [NOUT][LDA] fp32

    const int tid  = threadIdx.x;
    const int wid  = tid >> 5;
    const int lane = tid & 31;
    const int wm   = wid & 1;              // warp row 0..1 (32 rows each)
    const int wn   = wid >> 1;             // warp col 0..3 (NC cols each)
    const int row0 = blockIdx.x * 64;
    const int qr   = lane >> 2;
    const int qc   = lane & 3;

    // ---- stage A tile (coalesced float4, zero-fill OOB rows) ----
    #pragma unroll
    for (int it = 0; it < 8; ++it) {
        int idx = tid + it * 256;
        int r = idx >> 5, c4 = idx & 31;
        int row = row0 + r;
        float4 v = make_float4(0.f, 0.f, 0.f, 0.f);
        if (row < N) v = reinterpret_cast<const float4*>(A)[(size_t)row * 32 + c4];
        *reinterpret_cast<float4*>(As + r * LDA + c4 * 4) = v;
    }
    // ---- stage W tile raw ----
    #pragma unroll
    for (int it = 0; it < NOUT / 8; ++it) {
        int idx = tid + it * 256;
        int r = idx >> 5, c4 = idx & 31;
        float4 v = reinterpret_cast<const float4*>(W)[(size_t)r * 32 + c4];
        *reinterpret_cast<float4*>(Bs + r * LDA + c4 * 4) = v;
    }
    __syncthreads();

    float acc[2][NI][4];
    #pragma unroll
    for (int mi = 0; mi < 2; ++mi)
        #pragma unroll
        for (int ni = 0; ni < NI; ++ni)
            #pragma unroll
            for (int c = 0; c < 4; ++c) acc[mi][ni][c] = 0.f;

    // ldmatrix lane-constant bases
    uint32_t sb;
    asm("{ .reg .u64 t; cvta.to.shared.u64 t, %1; cvt.u32.u64 %0, t; }" : "=r"(sb) : "l"(sm));
    const uint32_t sB = sb + 64u * LDA * 4u;
    const int m  = lane >> 3;
    const int mr = ((m >> 1) << 3) + (lane & 7);   // row within 16-row group
    const uint32_t mc = (uint32_t)(m & 1) * 16u;
    const uint32_t aBase0 = sb + (uint32_t)(wm * 32 + mr) * (LDA * 4u) + mc;
    const uint32_t aBase1 = aBase0 + 16u * (LDA * 4u);
    const uint32_t bBase0 = sB + (uint32_t)(wn * NC + mr) * (LDA * 4u) + mc;
    const uint32_t bBase1 = bBase0 + 16u * (LDA * 4u);

    // double-buffered fragments: prefetch ks+1 before MMAs of ks
    uint32_t a0[2][4], a1[2][4], br0[2][4], br1[2][4];
    LDSM4(a0[0], aBase0);
    LDSM4(a1[0], aBase1);
    LDSM4(br0[0], bBase0);
    if (NI == 4) LDSM4(br1[0], bBase1);

    #pragma unroll
    for (int ks = 0; ks < 16; ++ks) {
        const int cur = ks & 1, nxt = cur ^ 1;
        if (ks < 15) {
            const uint32_t ko = (uint32_t)(ks + 1) * 32u;
            LDSM4(a0[nxt], aBase0 + ko);
            LDSM4(a1[nxt], aBase1 + ko);
            LDSM4(br0[nxt], bBase0 + ko);
            if (NI == 4) LDSM4(br1[nxt], bBase1 + ko);
        }

        uint32_t ah[2][4], al[2][4];
        SPLIT4(ah[0], al[0], a0[cur]);
        SPLIT4(ah[1], al[1], a1[cur]);
        uint32_t bh0[4], bl0[4], bh1[4], bl1[4];
        SPLIT4(bh0, bl0, br0[cur]);
        if (NI == 4) SPLIT4(bh1, bl1, br1[cur]);

        #pragma unroll
        for (int mi = 0; mi < 2; ++mi) {
            MMA_TF32(acc[mi][0], ah[mi], bh0[0], bh0[1]);
            MMA_TF32(acc[mi][1], ah[mi], bh0[2], bh0[3]);
            if (NI == 4) {
                MMA_TF32(acc[mi][2], ah[mi], bh1[0], bh1[1]);
                MMA_TF32(acc[mi][3], ah[mi], bh1[2], bh1[3]);
            }
        }
        #pragma unroll
        for (int mi = 0; mi < 2; ++mi) {
            MMA_TF32(acc[mi][0], ah[mi], bl0[0], bl0[1]);
            MMA_TF32(acc[mi][1], ah[mi], bl0[2], bl0[3]);
            if (NI == 4) {
                MMA_TF32(acc[mi][2], ah[mi], bl1[0], bl1[1]);
                MMA_TF32(acc[mi][3], ah[mi], bl1[2], bl1[3]);
            }
        }
        #pragma unroll
        for (int mi = 0; mi < 2; ++mi) {
            MMA_TF32(acc[mi][0], al[mi], bh0[0], bh0[1]);
            MMA_TF32(acc[mi][1], al[mi], bh0[2], bh0[3]);
            if (NI == 4) {
                MMA_TF32(acc[mi][2], al[mi], bh1[0], bh1[1]);
                MMA_TF32(acc[mi][3], al[mi], bh1[2], bh1[3]);
            }
        }
    }

    // ---- epilogue: bias + act, float2 stores ----
    const int rbase = row0 + wm * 32 + qr;
    const int cbase = wn * NC + qc * 2;
    #pragma unroll
    for (int ni = 0; ni < NI; ++ni) {
        int c = cbase + ni * 8;
        float b0 = __ldg(bias + c), b1 = __ldg(bias + c + 1);
        #pragma unroll
        for (int mi = 0; mi < 2; ++mi) {
            int r = rbase + mi * 16;
            float v0 = acc[mi][ni][0] + b0;
            float v1 = acc[mi][ni][1] + b1;
            float v2 = acc[mi][ni][2] + b0;
            float v3 = acc[mi][ni][3] + b1;
            if (RELU) {
                v0 = fmaxf(v0, 0.f); v1 = fmaxf(v1, 0.f);
                v2 = fmaxf(v2, 0.f); v3 = fmaxf(v3, 0.f);
            }
            if (r < N)
                *reinterpret_cast<float2*>(out + (size_t)r * NOUT + c) = make_float2(v0, v1);
            if (r + 8 < N)
                *reinterpret_cast<float2*>(out + (size_t)(r + 8) * NOUT + c) = make_float2(v2, v3);
        }
    }
}

// ---------------- CSR build ---------------------------------------------------
__global__ void zero_int_kernel(int* p, int n) {
    int i = blockIdx.x * blockDim.x + threadIdx.x;
    if (i < n) p[i] = 0;
}
__global__ void hist_kernel(const int* __restrict__ dst, int E, int* __restrict__ deg) {
    int i = blockIdx.x * blockDim.x + threadIdx.x;
    if (i < E) atomicAdd(&deg[dst[i]], 1);
}
__global__ void csr_scan1(const int* __restrict__ deg, int* __restrict__ off,
                          int* __restrict__ bsum, float* __restrict__ invd,
                          int* __restrict__ cnt, int n) {
    __shared__ int s[1024];
    int g = blockIdx.x * 1024 + threadIdx.x;
    int v = (g < n) ? deg[g] : 0;
    if (g < n) { invd[g] = 1.0f / fmaxf((float)v, 1.0f); cnt[g] = 0; }
    s[threadIdx.x] = v;
    __syncthreads();
    #pragma unroll
    for (int d = 1; d < 1024; d <<= 1) {
        int t = (threadIdx.x >= d) ? s[threadIdx.x - d] : 0;
        __syncthreads();
        s[threadIdx.x] += t;
        __syncthreads();
    }
    if (g < n) off[g + 1] = s[threadIdx.x];
    if (threadIdx.x == 1023) bsum[blockIdx.x] = s[1023];
}
__global__ void csr_scan2(int* bsum, int nb) {
    __shared__ int s[128];
    int v = (threadIdx.x < nb) ? bsum[threadIdx.x] : 0;
    s[threadIdx.x] = v;
    __syncthreads();
    #pragma unroll
    for (int d = 1; d < 128; d <<= 1) {
        int t = (threadIdx.x >= d) ? s[threadIdx.x - d] : 0;
        __syncthreads();
        s[threadIdx.x] += t;
        __syncthreads();
    }
    if (threadIdx.x < nb) bsum[threadIdx.x] = s[threadIdx.x] - v;  // exclusive
}
__global__ void csr_scan3(int* __restrict__ off, const int* __restrict__ bsum, int n) {
    int g = blockIdx.x * 1024 + threadIdx.x;
    if (g < n) off[g + 1] += bsum[blockIdx.x];
    if (g == 0) off[0] = 0;
}
__global__ void csr_fill(const int* __restrict__ src, const int* __restrict__ dst,
                         const int* __restrict__ off, int* __restrict__ cnt,
                         int* __restrict__ csrc, int E) {
    int i = blockIdx.x * blockDim.x + threadIdx.x;
    if (i < E) {
        int d = dst[i];
        int p = off[d] + atomicAdd(&cnt[d], 1);
        csrc[p] = src[i];
    }
}

// ---------------- fused mean-aggregate: out = h + mean_in(h) ------------------
// one warp per node, gather incoming src rows via CSR
__global__ void aggregate_kernel(const float* __restrict__ h, const int* __restrict__ off,
                                 const int* __restrict__ csrc, const float* __restrict__ invd,
                                 float* __restrict__ out, int N)
{
    int wid  = threadIdx.x >> 5;
    int lane = threadIdx.x & 31;
    int node = blockIdx.x * (blockDim.x >> 5) + wid;
    if (node >= N) return;
    int beg = off[node], end = off[node + 1];
    float4 acc = make_float4(0.f, 0.f, 0.f, 0.f);
    const float4* h4 = reinterpret_cast<const float4*>(h);
    int e = beg;
    for (; e + 1 < end; e += 2) {
        int s0 = __ldg(csrc + e), s1 = __ldg(csrc + e + 1);
        float4 v0 = __ldg(h4 + s0 * 32 + lane);
        float4 v1 = __ldg(h4 + s1 * 32 + lane);
        acc.x += v0.x + v1.x; acc.y += v0.y + v1.y;
        acc.z += v0.z + v1.z; acc.w += v0.w + v1.w;
    }
    if (e < end) {
        int s0 = __ldg(csrc + e);
        float4 v0 = __ldg(h4 + s0 * 32 + lane);
        acc.x += v0.x; acc.y += v0.y; acc.z += v0.z; acc.w += v0.w;
    }
    float iv = invd[node];
    float4 b = __ldg(h4 + node * 32 + lane);
    reinterpret_cast<float4*>(out)[node * 32 + lane] =
        make_float4(b.x + acc.x * iv, b.y + acc.y * iv,
                    b.z + acc.z * iv, b.w + acc.w * iv);
}

// ---------------- launch -----------------------------------------------------
extern "C" void kernel_launch(void* const* d_in, const int* in_sizes, int n_in,
                              void* d_out, int out_size)
{
    const float* x   = (const float*)d_in[0];
    const int*   src = (const int*)  d_in[1];
    const int*   dst = (const int*)  d_in[2];
    const float* W1  = (const float*)d_in[3];
    const float* b1  = (const float*)d_in[4];
    const float* W2  = (const float*)d_in[5];
    const float* b2  = (const float*)d_in[6];
    const float* W3  = (const float*)d_in[7];
    const float* b3  = (const float*)d_in[8];
    const float* Wo1 = (const float*)d_in[9];
    const float* bo1 = (const float*)d_in[10];
    const float* Wo2 = (const float*)d_in[11];
    const float* bo2 = (const float*)d_in[12];
    float* out = (float*)d_out;

    const int N = in_sizes[0] / FD;    // 100000
    const int E = in_sizes[1];         // 800000

    float *bufA, *bufB, *bufC, *invd;
    int *deg, *off, *cnt, *bsum, *csrc;
    cudaGetSymbolAddress((void**)&bufA, g_bufA);
    cudaGetSymbolAddress((void**)&bufB, g_bufB);
    cudaGetSymbolAddress((void**)&bufC, g_bufC);
    cudaGetSymbolAddress((void**)&invd, g_invdeg);
    cudaGetSymbolAddress((void**)&deg,  g_deg);
    cudaGetSymbolAddress((void**)&off,  g_off);
    cudaGetSymbolAddress((void**)&cnt,  g_cnt);
    cudaGetSymbolAddress((void**)&bsum, g_bsum);
    cudaGetSymbolAddress((void**)&csrc, g_csrc);

    const int smem128 = (64 + 128) * 140 * (int)sizeof(float);  // 107520
    const int smem64  = (64 + 64)  * 140 * (int)sizeof(float);  // 71680
    cudaFuncSetAttribute(gemm_mma<128, true >, cudaFuncAttributeMaxDynamicSharedMemorySize, smem128);
    cudaFuncSetAttribute(gemm_mma<128, false>, cudaFuncAttributeMaxDynamicSharedMemorySize, smem128);
    cudaFuncSetAttribute(gemm_mma<64,  false>, cudaFuncAttributeMaxDynamicSharedMemorySize, smem64);

    const int gb = (N + 63) / 64;                 // 1563 row blocks
    const int nb = (N + 1023) / 1024;             // 98 scan blocks
    const int ag = (N + 7) / 8;                   // aggregate: 8 warps/block

    // ---- CSR build (once per call; reused by both aggregations) ----
    zero_int_kernel<<<(N + 255) / 256, 256>>>(deg, N);
    hist_kernel<<<(E + 255) / 256, 256>>>(dst, E, deg);
    csr_scan1<<<nb, 1024>>>(deg, off, bsum, invd, cnt, N);
    csr_scan2<<<1, 128>>>(bsum, nb);
    csr_scan3<<<nb, 1024>>>(off, bsum, N);
    csr_fill<<<(E + 255) / 256, 256>>>(src, dst, off, cnt, csrc, E);

    // x2 = lin(relu(lin(x,W1,b1)),W2,b2)
    gemm_mma<128, true ><<<gb, 256, smem128>>>(x,    W1, b1, bufA, N);
    gemm_mma<128, false><<<gb, 256, smem128>>>(bufA, W2, b2, bufB, N);

    // h = x2 + mean_agg(x2)
    aggregate_kernel<<<ag, 256>>>(bufB, off, csrc, invd, bufA, N);

    // h = lin(relu(lin(h,W1,b1)),W2,b2)
    gemm_mma<128, true ><<<gb, 256, smem128>>>(bufA, W1, b1, bufC, N);
    gemm_mma<128, false><<<gb, 256, smem128>>>(bufC, W2, b2, bufB, N);

    // h = relu(lin(h,W3,b3))
    gemm_mma<128, true ><<<gb, 256, smem128>>>(bufB, W3, b3, bufA, N);

    // h = h + mean_agg(h)
    aggregate_kernel<<<ag, 256>>>(bufA, off, csrc, invd, bufB, N);

    // h = relu(lin(h,W3,b3)); h = relu(lin(h,Wo1,bo1)); out = lin(h,Wo2,bo2)
    gemm_mma<128, true ><<<gb, 256, smem128>>>(bufB, W3,  b3,  bufA, N);
    gemm_mma<128, true ><<<gb, 256, smem128>>>(bufA, Wo1, bo1, bufB, N);
    gemm_mma<64,  false><<<gb, 256, smem64 >>>(bufB, Wo2, bo2, out,  N);
}

// round 8
// speedup vs baseline: 4.8086x; 1.2752x over previous
#include <cuda_runtime.h>
#include <cstdint>

#define NN 100000
#define EE 800000
#define FD 128

// ---------------- scratch (device globals; no allocations allowed) ----------
__device__ float g_bufA[NN * FD];
__device__ float g_bufB[NN * FD];
__device__ float g_bufC[NN * FD];
__device__ float g_invdeg[NN];
__device__ int   g_deg[NN];
__device__ int   g_off[NN + 1];
__device__ int   g_cnt[NN];
__device__ int   g_bsum[128];
__device__ int   g_csrc[EE];

// ---------------- helpers ----------------------------------------------------
#define LDSM4(q, addr)                                                        \
    asm volatile("ldmatrix.sync.aligned.m8n8.x4.shared.b16 {%0,%1,%2,%3}, [%4];" \
        : "=r"((q)[0]), "=r"((q)[1]), "=r"((q)[2]), "=r"((q)[3]) : "r"(addr))

// pack two f32 -> bf16x2 (hi arg -> upper half, lo arg -> lower half)
__device__ __forceinline__ uint32_t packbf(float hi, float lo) {
    uint32_t d;
    asm("cvt.rn.bf16x2.f32 %0, %1, %2;" : "=r"(d) : "f"(hi), "f"(lo));
    return d;
}

// A fragment regs from our ldmatrix address pattern come as
// {(m0-7,k0-7),(m0-7,k8-15),(m8-15,k0-7),(m8-15,k8-15)} -> mma order {0,2,1,3}
#define MMA_BF16(d, a, b0, b1)                                                \
    asm volatile(                                                             \
        "mma.sync.aligned.m16n8k16.row.col.f32.bf16.bf16.f32 "                \
        "{%0,%1,%2,%3}, {%4,%5,%6,%7}, {%8,%9}, {%0,%1,%2,%3};"               \
        : "+f"((d)[0]), "+f"((d)[1]), "+f"((d)[2]), "+f"((d)[3])              \
        : "r"((a)[0]), "r"((a)[2]), "r"((a)[1]), "r"((a)[3]),                 \
          "r"(b0), "r"(b1))

// ---------------- split-BF16 mma.sync GEMM ------------------------------------
// out[i][j] = act( sum_k in[i][k] * W[j][k] + b[j] )
// CTA: 256 threads = 8 warps (2m x 4n). Tile 64 x NOUT, K=128 single pass.
// A and W are split into bf16 hi/lo planes in smem at staging time
// (x = hi + lo, residual ~2^-18). Inner loop is pure ldmatrix.b16 + mma:
//   acc += Ah*Bh + Ah*Bl + Al*Bh   (lo*lo dropped).
// smem ~102KB -> 2 CTAs/SM overlap; k-loop software-pipelined.
template<int NOUT, bool RELU>
__global__ void __launch_bounds__(256, 2)
gemm_mma(const float* __restrict__ A, const float* __restrict__ W,
         const float* __restrict__ bias, float* __restrict__ out, int N)
{
    constexpr int LDH  = 136;             // halves per row (272B): conflict-free
    constexpr int NC   = NOUT / 4;        // cols per n-warp: 32 or 16
    constexpr int NT   = NC / 16;         // n16 ldmatrix tiles per warp: 2 or 1
    constexpr int ROWB = LDH * 2;         // row stride in bytes
    extern __shared__ uint16_t smh[];
    // layout (halves): Ahi[64][LDH], Alo[64][LDH], Bhi[NOUT][LDH], Blo[NOUT][LDH]
    uint32_t* AhiU = reinterpret_cast<uint32_t*>(smh);
    uint32_t* AloU = AhiU + 64 * (LDH / 2);
    uint32_t* BhiU = AloU + 64 * (LDH / 2);
    uint32_t* BloU = BhiU + NOUT * (LDH / 2);

    const int tid  = threadIdx.x;
    const int wid  = tid >> 5;
    const int lane = tid & 31;
    const int wm   = wid & 1;              // warp row 0..1 (32 rows each)
    const int wn   = wid >> 1;             // warp col 0..3 (NC cols each)
    const int row0 = blockIdx.x * 64;
    const int qr   = lane >> 2;
    const int qc   = lane & 3;

    // ---- stage A tile: fp32 -> bf16 hi/lo planes ----
    #pragma unroll
    for (int it = 0; it < 8; ++it) {
        int idx = tid + it * 256;
        int r = idx >> 5, c4 = idx & 31;
        int row = row0 + r;
        float4 v = make_float4(0.f, 0.f, 0.f, 0.f);
        if (row < N) v = reinterpret_cast<const float4*>(A)[(size_t)row * 32 + c4];
        uint32_t p01 = packbf(v.y, v.x);
        uint32_t p23 = packbf(v.w, v.z);
        float hx = __uint_as_float(p01 << 16), hy = __uint_as_float(p01 & 0xFFFF0000u);
        float hz = __uint_as_float(p23 << 16), hw = __uint_as_float(p23 & 0xFFFF0000u);
        uint32_t l01 = packbf(v.y - hy, v.x - hx);
        uint32_t l23 = packbf(v.w - hw, v.z - hz);
        int o = r * (LDH / 2) + c4 * 2;
        AhiU[o] = p01; AhiU[o + 1] = p23;
        AloU[o] = l01; AloU[o + 1] = l23;
    }
    // ---- stage W tile: fp32 -> bf16 hi/lo planes ----
    #pragma unroll
    for (int it = 0; it < NOUT / 8; ++it) {
        int idx = tid + it * 256;
        int r = idx >> 5, c4 = idx & 31;
        float4 v = reinterpret_cast<const float4*>(W)[(size_t)r * 32 + c4];
        uint32_t p01 = packbf(v.y, v.x);
        uint32_t p23 = packbf(v.w, v.z);
        float hx = __uint_as_float(p01 << 16), hy = __uint_as_float(p01 & 0xFFFF0000u);
        float hz = __uint_as_float(p23 << 16), hw = __uint_as_float(p23 & 0xFFFF0000u);
        uint32_t l01 = packbf(v.y - hy, v.x - hx);
        uint32_t l23 = packbf(v.w - hw, v.z - hz);
        int o = r * (LDH / 2) + c4 * 2;
        BhiU[o] = p01; BhiU[o + 1] = p23;
        BloU[o] = l01; BloU[o + 1] = l23;
    }
    __syncthreads();

    constexpr int NI = NT * 2;             // n8 frags per warp: 4 or 2
    float acc[2][NI][4];
    #pragma unroll
    for (int mi = 0; mi < 2; ++mi)
        #pragma unroll
        for (int ni = 0; ni < NI; ++ni)
            #pragma unroll
            for (int c = 0; c < 4; ++c) acc[mi][ni][c] = 0.f;

    // ldmatrix lane-constant bases: lanes 0-7 rows 0-7 (+0B), 8-15 rows 0-7
    // (+16B), 16-23 rows 8-15 (+0B), 24-31 rows 8-15 (+16B)
    uint32_t sb;
    asm("{ .reg .u64 t; cvta.to.shared.u64 t, %1; cvt.u32.u64 %0, t; }" : "=r"(sb) : "l"(smh));
    const int m  = lane >> 3;
    const int mr = ((m >> 1) << 3) + (lane & 7);
    const uint32_t mc = (uint32_t)(m & 1) * 16u;
    const uint32_t oAhi = 0, oAlo = 64u * ROWB;
    const uint32_t oBhi = 2u * 64u * ROWB;
    const uint32_t oBlo = oBhi + (uint32_t)NOUT * ROWB;

    uint32_t aBaseH[2], aBaseL[2], bBaseH[NT], bBaseL[NT];
    #pragma unroll
    for (int mi = 0; mi < 2; ++mi) {
        uint32_t ro = (uint32_t)(wm * 32 + mi * 16 + mr) * ROWB + mc;
        aBaseH[mi] = sb + oAhi + ro;
        aBaseL[mi] = sb + oAlo + ro;
    }
    #pragma unroll
    for (int t = 0; t < NT; ++t) {
        uint32_t ro = (uint32_t)(wn * NC + t * 16 + mr) * ROWB + mc;
        bBaseH[t] = sb + oBhi + ro;
        bBaseL[t] = sb + oBlo + ro;
    }

    // double-buffered fragments: prefetch ks+1 before MMAs of ks
    uint32_t aH[2][2][4], aL[2][2][4], bH[2][NT][4], bL[2][NT][4];
    #pragma unroll
    for (int mi = 0; mi < 2; ++mi) { LDSM4(aH[0][mi], aBaseH[mi]); LDSM4(aL[0][mi], aBaseL[mi]); }
    #pragma unroll
    for (int t = 0; t < NT; ++t)   { LDSM4(bH[0][t], bBaseH[t]);   LDSM4(bL[0][t], bBaseL[t]); }

    #pragma unroll
    for (int ks = 0; ks < 8; ++ks) {          // k16 per step
        const int cur = ks & 1, nxt = cur ^ 1;
        if (ks < 7) {
            const uint32_t ko = (uint32_t)(ks + 1) * 32u;   // 16 halves = 32B
            #pragma unroll
            for (int mi = 0; mi < 2; ++mi) {
                LDSM4(aH[nxt][mi], aBaseH[mi] + ko);
                LDSM4(aL[nxt][mi], aBaseL[mi] + ko);
            }
            #pragma unroll
            for (int t = 0; t < NT; ++t) {
                LDSM4(bH[nxt][t], bBaseH[t] + ko);
                LDSM4(bL[nxt][t], bBaseL[t] + ko);
            }
        }

        #pragma unroll
        for (int mi = 0; mi < 2; ++mi)
            #pragma unroll
            for (int t = 0; t < NT; ++t) {
                MMA_BF16(acc[mi][t * 2 + 0], aH[cur][mi], bH[cur][t][0], bH[cur][t][1]);
                MMA_BF16(acc[mi][t * 2 + 1], aH[cur][mi], bH[cur][t][2], bH[cur][t][3]);
            }
        #pragma unroll
        for (int mi = 0; mi < 2; ++mi)
            #pragma unroll
            for (int t = 0; t < NT; ++t) {
                MMA_BF16(acc[mi][t * 2 + 0], aH[cur][mi], bL[cur][t][0], bL[cur][t][1]);
                MMA_BF16(acc[mi][t * 2 + 1], aH[cur][mi], bL[cur][t][2], bL[cur][t][3]);
            }
        #pragma unroll
        for (int mi = 0; mi < 2; ++mi)
            #pragma unroll
            for (int t = 0; t < NT; ++t) {
                MMA_BF16(acc[mi][t * 2 + 0], aL[cur][mi], bH[cur][t][0], bH[cur][t][1]);
                MMA_BF16(acc[mi][t * 2 + 1], aL[cur][mi], bH[cur][t][2], bH[cur][t][3]);
            }
    }

    // ---- epilogue: bias + act, float2 stores ----
    const int rbase = row0 + wm * 32 + qr;
    const int cbase = wn * NC + qc * 2;
    #pragma unroll
    for (int ni = 0; ni < NI; ++ni) {
        int c = cbase + ni * 8;
        float b0 = __ldg(bias + c), b1 = __ldg(bias + c + 1);
        #pragma unroll
        for (int mi = 0; mi < 2; ++mi) {
            int r = rbase + mi * 16;
            float v0 = acc[mi][ni][0] + b0;
            float v1 = acc[mi][ni][1] + b1;
            float v2 = acc[mi][ni][2] + b0;
            float v3 = acc[mi][ni][3] + b1;
            if (RELU) {
                v0 = fmaxf(v0, 0.f); v1 = fmaxf(v1, 0.f);
                v2 = fmaxf(v2, 0.f); v3 = fmaxf(v3, 0.f);
            }
            if (r < N)
                *reinterpret_cast<float2*>(out + (size_t)r * NOUT + c) = make_float2(v0, v1);
            if (r + 8 < N)
                *reinterpret_cast<float2*>(out + (size_t)(r + 8) * NOUT + c) = make_float2(v2, v3);
        }
    }
}

// ---------------- CSR build ---------------------------------------------------
__global__ void zero_int_kernel(int* p, int n) {
    int i = blockIdx.x * blockDim.x + threadIdx.x;
    if (i < n) p[i] = 0;
}
__global__ void hist_kernel(const int* __restrict__ dst, int E, int* __restrict__ deg) {
    int i = blockIdx.x * blockDim.x + threadIdx.x;
    if (i < E) atomicAdd(&deg[dst[i]], 1);
}
__global__ void csr_scan1(const int* __restrict__ deg, int* __restrict__ off,
                          int* __restrict__ bsum, float* __restrict__ invd,
                          int* __restrict__ cnt, int n) {
    __shared__ int s[1024];
    int g = blockIdx.x * 1024 + threadIdx.x;
    int v = (g < n) ? deg[g] : 0;
    if (g < n) { invd[g] = 1.0f / fmaxf((float)v, 1.0f); cnt[g] = 0; }
    s[threadIdx.x] = v;
    __syncthreads();
    #pragma unroll
    for (int d = 1; d < 1024; d <<= 1) {
        int t = (threadIdx.x >= d) ? s[threadIdx.x - d] : 0;
        __syncthreads();
        s[threadIdx.x] += t;
        __syncthreads();
    }
    if (g < n) off[g + 1] = s[threadIdx.x];
    if (threadIdx.x == 1023) bsum[blockIdx.x] = s[1023];
}
__global__ void csr_scan2(int* bsum, int nb) {
    __shared__ int s[128];
    int v = (threadIdx.x < nb) ? bsum[threadIdx.x] : 0;
    s[threadIdx.x] = v;
    __syncthreads();
    #pragma unroll
    for (int d = 1; d < 128; d <<= 1) {
        int t = (threadIdx.x >= d) ? s[threadIdx.x - d] : 0;
        __syncthreads();
        s[threadIdx.x] += t;
        __syncthreads();
    }
    if (threadIdx.x < nb) bsum[threadIdx.x] = s[threadIdx.x] - v;  // exclusive
}
__global__ void csr_scan3(int* __restrict__ off, const int* __restrict__ bsum, int n) {
    int g = blockIdx.x * 1024 + threadIdx.x;
    if (g < n) off[g + 1] += bsum[blockIdx.x];
    if (g == 0) off[0] = 0;
}
__global__ void csr_fill(const int* __restrict__ src, const int* __restrict__ dst,
                         const int* __restrict__ off, int* __restrict__ cnt,
                         int* __restrict__ csrc, int E) {
    int i = blockIdx.x * blockDim.x + threadIdx.x;
    if (i < E) {
        int d = dst[i];
        int p = off[d] + atomicAdd(&cnt[d], 1);
        csrc[p] = src[i];
    }
}

// ---------------- fused mean-aggregate: out = h + mean_in(h) ------------------
// one warp per node, gather incoming src rows via CSR
__global__ void aggregate_kernel(const float* __restrict__ h, const int* __restrict__ off,
                                 const int* __restrict__ csrc, const float* __restrict__ invd,
                                 float* __restrict__ out, int N)
{
    int wid  = threadIdx.x >> 5;
    int lane = threadIdx.x & 31;
    int node = blockIdx.x * (blockDim.x >> 5) + wid;
    if (node >= N) return;
    int beg = off[node], end = off[node + 1];
    float4 acc = make_float4(0.f, 0.f, 0.f, 0.f);
    const float4* h4 = reinterpret_cast<const float4*>(h);
    int e = beg;
    for (; e + 1 < end; e += 2) {
        int s0 = __ldg(csrc + e), s1 = __ldg(csrc + e + 1);
        float4 v0 = __ldg(h4 + s0 * 32 + lane);
        float4 v1 = __ldg(h4 + s1 * 32 + lane);
        acc.x += v0.x + v1.x; acc.y += v0.y + v1.y;
        acc.z += v0.z + v1.z; acc.w += v0.w + v1.w;
    }
    if (e < end) {
        int s0 = __ldg(csrc + e);
        float4 v0 = __ldg(h4 + s0 * 32 + lane);
        acc.x += v0.x; acc.y += v0.y; acc.z += v0.z; acc.w += v0.w;
    }
    float iv = invd[node];
    float4 b = __ldg(h4 + node * 32 + lane);
    reinterpret_cast<float4*>(out)[node * 32 + lane] =
        make_float4(b.x + acc.x * iv, b.y + acc.y * iv,
                    b.z + acc.z * iv, b.w + acc.w * iv);
}

// ---------------- launch -----------------------------------------------------
extern "C" void kernel_launch(void* const* d_in, const int* in_sizes, int n_in,
                              void* d_out, int out_size)
{
    const float* x   = (const float*)d_in[0];
    const int*   src = (const int*)  d_in[1];
    const int*   dst = (const int*)  d_in[2];
    const float* W1  = (const float*)d_in[3];
    const float* b1  = (const float*)d_in[4];
    const float* W2  = (const float*)d_in[5];
    const float* b2  = (const float*)d_in[6];
    const float* W3  = (const float*)d_in[7];
    const float* b3  = (const float*)d_in[8];
    const float* Wo1 = (const float*)d_in[9];
    const float* bo1 = (const float*)d_in[10];
    const float* Wo2 = (const float*)d_in[11];
    const float* bo2 = (const float*)d_in[12];
    float* out = (float*)d_out;

    const int N = in_sizes[0] / FD;    // 100000
    const int E = in_sizes[1];         // 800000

    float *bufA, *bufB, *bufC, *invd;
    int *deg, *off, *cnt, *bsum, *csrc;
    cudaGetSymbolAddress((void**)&bufA, g_bufA);
    cudaGetSymbolAddress((void**)&bufB, g_bufB);
    cudaGetSymbolAddress((void**)&bufC, g_bufC);
    cudaGetSymbolAddress((void**)&invd, g_invdeg);
    cudaGetSymbolAddress((void**)&deg,  g_deg);
    cudaGetSymbolAddress((void**)&off,  g_off);
    cudaGetSymbolAddress((void**)&cnt,  g_cnt);
    cudaGetSymbolAddress((void**)&bsum, g_bsum);
    cudaGetSymbolAddress((void**)&csrc, g_csrc);

    const int smem128 = 2 * (64 + 128) * 136 * 2;   // 104448 B
    const int smem64  = 2 * (64 + 64)  * 136 * 2;   // 69632 B
    cudaFuncSetAttribute(gemm_mma<128, true >, cudaFuncAttributeMaxDynamicSharedMemorySize, smem128);
    cudaFuncSetAttribute(gemm_mma<128, false>, cudaFuncAttributeMaxDynamicSharedMemorySize, smem128);
    cudaFuncSetAttribute(gemm_mma<64,  false>, cudaFuncAttributeMaxDynamicSharedMemorySize, smem64);

    const int gb = (N + 63) / 64;                 // 1563 row blocks
    const int nb = (N + 1023) / 1024;             // 98 scan blocks
    const int ag = (N + 7) / 8;                   // aggregate: 8 warps/block

    // ---- CSR build (once per call; reused by both aggregations) ----
    zero_int_kernel<<<(N + 255) / 256, 256>>>(deg, N);
    hist_kernel<<<(E + 255) / 256, 256>>>(dst, E, deg);
    csr_scan1<<<nb, 1024>>>(deg, off, bsum, invd, cnt, N);
    csr_scan2<<<1, 128>>>(bsum, nb);
    csr_scan3<<<nb, 1024>>>(off, bsum, N);
    csr_fill<<<(E + 255) / 256, 256>>>(src, dst, off, cnt, csrc, E);

    // x2 = lin(relu(lin(x,W1,b1)),W2,b2)
    gemm_mma<128, true ><<<gb, 256, smem128>>>(x,    W1, b1, bufA, N);
    gemm_mma<128, false><<<gb, 256, smem128>>>(bufA, W2, b2, bufB, N);

    // h = x2 + mean_agg(x2)
    aggregate_kernel<<<ag, 256>>>(bufB, off, csrc, invd, bufA, N);

    // h = lin(relu(lin(h,W1,b1)),W2,b2)
    gemm_mma<128, true ><<<gb, 256, smem128>>>(bufA, W1, b1, bufC, N);
    gemm_mma<128, false><<<gb, 256, smem128>>>(bufC, W2, b2, bufB, N);

    // h = relu(lin(h,W3,b3))
    gemm_mma<128, true ><<<gb, 256, smem128>>>(bufB, W3, b3, bufA, N);

    // h = h + mean_agg(h)
    aggregate_kernel<<<ag, 256>>>(bufA, off, csrc, invd, bufB, N);

    // h = relu(lin(h,W3,b3)); h = relu(lin(h,Wo1,bo1)); out = lin(h,Wo2,bo2)
    gemm_mma<128, true ><<<gb, 256, smem128>>>(bufB, W3,  b3,  bufA, N);
    gemm_mma<128, true ><<<gb, 256, smem128>>>(bufA, Wo1, bo1, bufB, N);
    gemm_mma<64,  false><<<gb, 256, smem64 >>>(bufB, Wo2, bo2, out,  N);
}

// round 9
// speedup vs baseline: 5.0343x; 1.0469x over previous
#include <cuda_runtime.h>
#include <cstdint>

#define NN 100000
#define EE 800000
#define FD 128

// ---------------- scratch (device globals; no allocations allowed) ----------
__device__ float g_bufA[NN * FD];
__device__ float g_bufB[NN * FD];
__device__ float g_invdeg[NN];
__device__ int   g_deg[NN];
__device__ int   g_off[NN + 1];
__device__ int   g_cnt[NN];
__device__ int   g_bsum[128];
__device__ int   g_csrc[EE];

// ---------------- helpers ----------------------------------------------------
#define LDSM4(q, addr)                                                        \
    asm volatile("ldmatrix.sync.aligned.m8n8.x4.shared.b16 {%0,%1,%2,%3}, [%4];" \
        : "=r"((q)[0]), "=r"((q)[1]), "=r"((q)[2]), "=r"((q)[3]) : "r"(addr))

// pack two f32 -> bf16x2 (hi arg -> upper half, lo arg -> lower half)
__device__ __forceinline__ uint32_t packbf(float hi, float lo) {
    uint32_t d;
    asm("cvt.rn.bf16x2.f32 %0, %1, %2;" : "=r"(d) : "f"(hi), "f"(lo));
    return d;
}

// A fragment regs from our ldmatrix address pattern come as
// {(m0-7,k0-7),(m0-7,k8-15),(m8-15,k0-7),(m8-15,k8-15)} -> mma order {0,2,1,3}
#define MMA_BF16(d, a, b0, b1)                                                \
    asm volatile(                                                             \
        "mma.sync.aligned.m16n8k16.row.col.f32.bf16.bf16.f32 "                \
        "{%0,%1,%2,%3}, {%4,%5,%6,%7}, {%8,%9}, {%0,%1,%2,%3};"               \
        : "+f"((d)[0]), "+f"((d)[1]), "+f"((d)[2]), "+f"((d)[3])              \
        : "r"((a)[0]), "r"((a)[2]), "r"((a)[1]), "r"((a)[3]),                 \
          "r"(b0), "r"(b1))

// split a float4 into bf16x2 hi/lo pair words
__device__ __forceinline__ void split4(float4 v, uint32_t& p01, uint32_t& p23,
                                       uint32_t& l01, uint32_t& l23) {
    p01 = packbf(v.y, v.x);
    p23 = packbf(v.w, v.z);
    float hx = __uint_as_float(p01 << 16), hy = __uint_as_float(p01 & 0xFFFF0000u);
    float hz = __uint_as_float(p23 << 16), hw = __uint_as_float(p23 & 0xFFFF0000u);
    l01 = packbf(v.y - hy, v.x - hx);
    l23 = packbf(v.w - hw, v.z - hz);
}

// ---------------- shared bf16 3-pass mainloop (K=128, 8 k16 steps) -----------
// acc layout: acc[mi * (2*NT) + t*2 + j][4]
template<int NT>
__device__ __forceinline__ void bf16_mainloop(
    uint32_t aBH0, uint32_t aBH1, uint32_t aBL0, uint32_t aBL1,
    const uint32_t* bBH, const uint32_t* bBL, float (*acc)[4])
{
    constexpr int NI = NT * 2;
    uint32_t aH[2][2][4], aL[2][2][4], bH[2][NT][4], bL[2][NT][4];
    LDSM4(aH[0][0], aBH0); LDSM4(aH[0][1], aBH1);
    LDSM4(aL[0][0], aBL0); LDSM4(aL[0][1], aBL1);
    #pragma unroll
    for (int t = 0; t < NT; ++t) { LDSM4(bH[0][t], bBH[t]); LDSM4(bL[0][t], bBL[t]); }

    #pragma unroll
    for (int ks = 0; ks < 8; ++ks) {
        const int cur = ks & 1, nxt = cur ^ 1;
        if (ks < 7) {
            const uint32_t ko = (uint32_t)(ks + 1) * 32u;   // 16 halves
            LDSM4(aH[nxt][0], aBH0 + ko); LDSM4(aH[nxt][1], aBH1 + ko);
            LDSM4(aL[nxt][0], aBL0 + ko); LDSM4(aL[nxt][1], aBL1 + ko);
            #pragma unroll
            for (int t = 0; t < NT; ++t) {
                LDSM4(bH[nxt][t], bBH[t] + ko);
                LDSM4(bL[nxt][t], bBL[t] + ko);
            }
        }
        #pragma unroll
        for (int mi = 0; mi < 2; ++mi)
            #pragma unroll
            for (int t = 0; t < NT; ++t) {
                MMA_BF16(acc[mi * NI + t * 2 + 0], aH[cur][mi], bH[cur][t][0], bH[cur][t][1]);
                MMA_BF16(acc[mi * NI + t * 2 + 1], aH[cur][mi], bH[cur][t][2], bH[cur][t][3]);
            }
        #pragma unroll
        for (int mi = 0; mi < 2; ++mi)
            #pragma unroll
            for (int t = 0; t < NT; ++t) {
                MMA_BF16(acc[mi * NI + t * 2 + 0], aH[cur][mi], bL[cur][t][0], bL[cur][t][1]);
                MMA_BF16(acc[mi * NI + t * 2 + 1], aH[cur][mi], bL[cur][t][2], bL[cur][t][3]);
            }
        #pragma unroll
        for (int mi = 0; mi < 2; ++mi)
            #pragma unroll
            for (int t = 0; t < NT; ++t) {
                MMA_BF16(acc[mi * NI + t * 2 + 0], aL[cur][mi], bH[cur][t][0], bH[cur][t][1]);
                MMA_BF16(acc[mi * NI + t * 2 + 1], aL[cur][mi], bH[cur][t][2], bH[cur][t][3]);
            }
    }
}

// ---------------- standalone split-BF16 GEMM (R8, unchanged behavior) --------
template<int NOUT, bool RELU>
__global__ void __launch_bounds__(256, 2)
gemm_mma(const float* __restrict__ A, const float* __restrict__ W,
         const float* __restrict__ bias, float* __restrict__ out, int N)
{
    constexpr int LDH = 136, LDU = 68;
    constexpr uint32_t ROWB = 272;
    constexpr int NC = NOUT / 4;
    constexpr int NT = NC / 16;
    constexpr int NI = NT * 2;
    extern __shared__ uint16_t smh[];
    uint32_t* AhiU = reinterpret_cast<uint32_t*>(smh);
    uint32_t* AloU = AhiU + 64 * LDU;
    uint32_t* BhiU = AloU + 64 * LDU;
    uint32_t* BloU = BhiU + NOUT * LDU;

    const int tid  = threadIdx.x;
    const int wid  = tid >> 5;
    const int lane = tid & 31;
    const int wm   = wid & 1;
    const int wn   = wid >> 1;
    const int row0 = blockIdx.x * 64;
    const int qr   = lane >> 2;
    const int qc   = lane & 3;

    #pragma unroll
    for (int it = 0; it < 8; ++it) {
        int idx = tid + it * 256;
        int r = idx >> 5, c4 = idx & 31;
        int row = row0 + r;
        float4 v = make_float4(0.f, 0.f, 0.f, 0.f);
        if (row < N) v = reinterpret_cast<const float4*>(A)[(size_t)row * 32 + c4];
        uint32_t p01, p23, l01, l23;
        split4(v, p01, p23, l01, l23);
        int o = r * LDU + c4 * 2;
        AhiU[o] = p01; AhiU[o + 1] = p23;
        AloU[o] = l01; AloU[o + 1] = l23;
    }
    #pragma unroll
    for (int it = 0; it < NOUT / 8; ++it) {
        int idx = tid + it * 256;
        int r = idx >> 5, c4 = idx & 31;
        float4 v = reinterpret_cast<const float4*>(W)[(size_t)r * 32 + c4];
        uint32_t p01, p23, l01, l23;
        split4(v, p01, p23, l01, l23);
        int o = r * LDU + c4 * 2;
        BhiU[o] = p01; BhiU[o + 1] = p23;
        BloU[o] = l01; BloU[o + 1] = l23;
    }
    __syncthreads();

    float acc[2 * NI][4];
    #pragma unroll
    for (int i = 0; i < 2 * NI; ++i)
        #pragma unroll
        for (int c = 0; c < 4; ++c) acc[i][c] = 0.f;

    uint32_t sb;
    asm("{ .reg .u64 t; cvta.to.shared.u64 t, %1; cvt.u32.u64 %0, t; }" : "=r"(sb) : "l"(smh));
    const int m  = lane >> 3;
    const int mr = ((m >> 1) << 3) + (lane & 7);
    const uint32_t mc = (uint32_t)(m & 1) * 16u;
    const uint32_t oAlo = 64u * ROWB;
    const uint32_t oBhi = 2u * 64u * ROWB;

    uint32_t aBH0 = sb + (uint32_t)(wm * 32 + 0  + mr) * ROWB + mc;
    uint32_t aBH1 = sb + (uint32_t)(wm * 32 + 16 + mr) * ROWB + mc;
    uint32_t bBH[NT], bBL[NT];
    #pragma unroll
    for (int t = 0; t < NT; ++t) {
        bBH[t] = sb + oBhi + (uint32_t)(wn * NC + t * 16 + mr) * ROWB + mc;
        bBL[t] = bBH[t] + (uint32_t)NOUT * ROWB;
    }
    bf16_mainloop<NT>(aBH0, aBH1, aBH0 + oAlo, aBH1 + oAlo, bBH, bBL, acc);

    const int rbase = row0 + wm * 32 + qr;
    const int cbase = wn * NC + qc * 2;
    #pragma unroll
    for (int ni = 0; ni < NI; ++ni) {
        int c = cbase + ni * 8;
        float b0 = __ldg(bias + c), b1 = __ldg(bias + c + 1);
        #pragma unroll
        for (int mi = 0; mi < 2; ++mi) {
            const float* a = acc[mi * NI + ni];
            int r = rbase + mi * 16;
            float v0 = a[0] + b0, v1 = a[1] + b1, v2 = a[2] + b0, v3 = a[3] + b1;
            if (RELU) {
                v0 = fmaxf(v0, 0.f); v1 = fmaxf(v1, 0.f);
                v2 = fmaxf(v2, 0.f); v3 = fmaxf(v3, 0.f);
            }
            if (r < N)
                *reinterpret_cast<float2*>(out + (size_t)r * NOUT + c) = make_float2(v0, v1);
            if (r + 8 < N)
                *reinterpret_cast<float2*>(out + (size_t)(r + 8) * NOUT + c) = make_float2(v2, v3);
        }
    }
}

// ---------------- fused 2-layer GEMM ------------------------------------------
// out = act2( relu( A @ W1^T + b1 ) @ W2^T + b2 )
// 512 threads = 16 warps (4m x 4n), tile 128 rows. Mid layer stays in smem
// as bf16 hi/lo planes (overwrites A planes) - no global round trip.
template<int NOUT2, bool RELU2>
__global__ void __launch_bounds__(512)
gemm_fused2(const float* __restrict__ A, const float* __restrict__ W1,
            const float* __restrict__ b1, const float* __restrict__ W2,
            const float* __restrict__ b2, float* __restrict__ out, int N)
{
    constexpr int LDH = 136, LDU = 68;
    constexpr uint32_t ROWB = 272;
    constexpr int PA = 128 * LDU;               // u32 per 128-row plane
    extern __shared__ uint16_t smh[];
    uint32_t* U    = reinterpret_cast<uint32_t*>(smh);
    uint32_t* AhiU = U;                          // also mid planes after GEMM1
    uint32_t* AloU = U + PA;
    uint32_t* B1h  = U + 2 * PA;
    uint32_t* B1l  = U + 3 * PA;
    uint32_t* B2h  = U + 4 * PA;
    uint32_t* B2l  = B2h + NOUT2 * LDU;

    const int tid  = threadIdx.x;
    const int wid  = tid >> 5;
    const int lane = tid & 31;
    const int wm   = wid & 3;                    // 4 m-warps x 32 rows
    const int wn   = wid >> 2;                   // 4 n-warps
    const int row0 = blockIdx.x * 128;
    const int qr   = lane >> 2;
    const int qc   = lane & 3;

    // ---- stage A ----
    #pragma unroll
    for (int it = 0; it < 8; ++it) {
        int idx = tid + it * 512;
        int r = idx >> 5, c4 = idx & 31;
        int row = row0 + r;
        float4 v = make_float4(0.f, 0.f, 0.f, 0.f);
        if (row < N) v = reinterpret_cast<const float4*>(A)[(size_t)row * 32 + c4];
        uint32_t p01, p23, l01, l23;
        split4(v, p01, p23, l01, l23);
        int o = r * LDU + c4 * 2;
        AhiU[o] = p01; AhiU[o + 1] = p23;
        AloU[o] = l01; AloU[o + 1] = l23;
    }
    // ---- stage W1 ----
    #pragma unroll
    for (int it = 0; it < 8; ++it) {
        int idx = tid + it * 512;
        int r = idx >> 5, c4 = idx & 31;
        float4 v = reinterpret_cast<const float4*>(W1)[(size_t)r * 32 + c4];
        uint32_t p01, p23, l01, l23;
        split4(v, p01, p23, l01, l23);
        int o = r * LDU + c4 * 2;
        B1h[o] = p01; B1h[o + 1] = p23;
        B1l[o] = l01; B1l[o + 1] = l23;
    }
    // ---- stage W2 ----
    #pragma unroll
    for (int it = 0; it < NOUT2 / 16; ++it) {
        int idx = tid + it * 512;
        int r = idx >> 5, c4 = idx & 31;
        float4 v = reinterpret_cast<const float4*>(W2)[(size_t)r * 32 + c4];
        uint32_t p01, p23, l01, l23;
        split4(v, p01, p23, l01, l23);
        int o = r * LDU + c4 * 2;
        B2h[o] = p01; B2h[o + 1] = p23;
        B2l[o] = l01; B2l[o + 1] = l23;
    }
    __syncthreads();

    uint32_t sb;
    asm("{ .reg .u64 t; cvta.to.shared.u64 t, %1; cvt.u32.u64 %0, t; }" : "=r"(sb) : "l"(smh));
    const int m  = lane >> 3;
    const int mr = ((m >> 1) << 3) + (lane & 7);
    const uint32_t mc = (uint32_t)(m & 1) * 16u;
    const uint32_t oAlo = (uint32_t)PA * 4u;

    const uint32_t aBH0 = sb + (uint32_t)(wm * 32 + 0  + mr) * ROWB + mc;
    const uint32_t aBH1 = sb + (uint32_t)(wm * 32 + 16 + mr) * ROWB + mc;

    // ---- GEMM1: 128 x 128, relu ----
    {
        float acc[8][4];
        #pragma unroll
        for (int i = 0; i < 8; ++i)
            #pragma unroll
            for (int c = 0; c < 4; ++c) acc[i][c] = 0.f;

        uint32_t bBH[2], bBL[2];
        const uint32_t oB1 = (uint32_t)(2 * PA) * 4u;
        #pragma unroll
        for (int t = 0; t < 2; ++t) {
            bBH[t] = sb + oB1 + (uint32_t)(wn * 32 + t * 16 + mr) * ROWB + mc;
            bBL[t] = bBH[t] + (uint32_t)PA * 4u;
        }
        bf16_mainloop<2>(aBH0, aBH1, aBH0 + oAlo, aBH1 + oAlo, bBH, bBL, acc);
        __syncthreads();   // all reads of A planes done

        // epilogue1: bias+relu, write mid bf16 hi/lo planes into A plane region
        const int cb1 = wn * 32 + qc * 2;
        #pragma unroll
        for (int ni = 0; ni < 4; ++ni) {
            int c = cb1 + ni * 8;
            float bb0 = __ldg(b1 + c), bb1 = __ldg(b1 + c + 1);
            #pragma unroll
            for (int mi = 0; mi < 2; ++mi) {
                const float* a = acc[mi * 4 + ni];
                float v0 = fmaxf(a[0] + bb0, 0.f), v1 = fmaxf(a[1] + bb1, 0.f);
                float v2 = fmaxf(a[2] + bb0, 0.f), v3 = fmaxf(a[3] + bb1, 0.f);
                int r = wm * 32 + mi * 16 + qr;
                uint32_t p = packbf(v1, v0);
                float h0 = __uint_as_float(p << 16), h1 = __uint_as_float(p & 0xFFFF0000u);
                uint32_t l = packbf(v1 - h1, v0 - h0);
                int o = r * LDU + (c >> 1);
                AhiU[o] = p; AloU[o] = l;
                p = packbf(v3, v2);
                h0 = __uint_as_float(p << 16); h1 = __uint_as_float(p & 0xFFFF0000u);
                l = packbf(v3 - h1, v2 - h0);
                o += 8 * LDU;
                AhiU[o] = p; AloU[o] = l;
            }
        }
    }
    __syncthreads();       // mid planes complete

    // ---- GEMM2: 128 x NOUT2 ----
    constexpr int NC2 = NOUT2 / 4;
    constexpr int NT2 = NC2 / 16;
    constexpr int NI2 = NT2 * 2;
    float acc2[2 * NI2][4];
    #pragma unroll
    for (int i = 0; i < 2 * NI2; ++i)
        #pragma unroll
        for (int c = 0; c < 4; ++c) acc2[i][c] = 0.f;

    uint32_t bBH2[NT2], bBL2[NT2];
    const uint32_t oB2 = (uint32_t)(4 * PA) * 4u;
    #pragma unroll
    for (int t = 0; t < NT2; ++t) {
        bBH2[t] = sb + oB2 + (uint32_t)(wn * NC2 + t * 16 + mr) * ROWB + mc;
        bBL2[t] = bBH2[t] + (uint32_t)NOUT2 * ROWB;
    }
    bf16_mainloop<NT2>(aBH0, aBH1, aBH0 + oAlo, aBH1 + oAlo, bBH2, bBL2, acc2);

    // ---- final epilogue ----
    const int rbase = row0 + wm * 32 + qr;
    const int cbase = wn * NC2 + qc * 2;
    #pragma unroll
    for (int ni = 0; ni < NI2; ++ni) {
        int c = cbase + ni * 8;
        float b0 = __ldg(b2 + c), b1v = __ldg(b2 + c + 1);
        #pragma unroll
        for (int mi = 0; mi < 2; ++mi) {
            const float* a = acc2[mi * NI2 + ni];
            int r = rbase + mi * 16;
            float v0 = a[0] + b0, v1 = a[1] + b1v, v2 = a[2] + b0, v3 = a[3] + b1v;
            if (RELU2) {
                v0 = fmaxf(v0, 0.f); v1 = fmaxf(v1, 0.f);
                v2 = fmaxf(v2, 0.f); v3 = fmaxf(v3, 0.f);
            }
            if (r < N)
                *reinterpret_cast<float2*>(out + (size_t)r * NOUT2 + c) = make_float2(v0, v1);
            if (r + 8 < N)
                *reinterpret_cast<float2*>(out + (size_t)(r + 8) * NOUT2 + c) = make_float2(v2, v3);
        }
    }
}

// ---------------- CSR build ---------------------------------------------------
__global__ void zero_int_kernel(int* p, int n) {
    int i = blockIdx.x * blockDim.x + threadIdx.x;
    if (i < n) p[i] = 0;
}
__global__ void hist_kernel(const int* __restrict__ dst, int E, int* __restrict__ deg) {
    int i = blockIdx.x * blockDim.x + threadIdx.x;
    if (i < E) atomicAdd(&deg[dst[i]], 1);
}
__global__ void csr_scan1(const int* __restrict__ deg, int* __restrict__ off,
                          int* __restrict__ bsum, float* __restrict__ invd,
                          int* __restrict__ cnt, int n) {
    __shared__ int s[1024];
    int g = blockIdx.x * 1024 + threadIdx.x;
    int v = (g < n) ? deg[g] : 0;
    if (g < n) { invd[g] = 1.0f / fmaxf((float)v, 1.0f); cnt[g] = 0; }
    s[threadIdx.x] = v;
    __syncthreads();
    #pragma unroll
    for (int d = 1; d < 1024; d <<= 1) {
        int t = (threadIdx.x >= d) ? s[threadIdx.x - d] : 0;
        __syncthreads();
        s[threadIdx.x] += t;
        __syncthreads();
    }
    if (g < n) off[g + 1] = s[threadIdx.x];
    if (threadIdx.x == 1023) bsum[blockIdx.x] = s[1023];
}
__global__ void csr_scan2(int* bsum, int nb) {
    __shared__ int s[128];
    int v = (threadIdx.x < nb) ? bsum[threadIdx.x] : 0;
    s[threadIdx.x] = v;
    __syncthreads();
    #pragma unroll
    for (int d = 1; d < 128; d <<= 1) {
        int t = (threadIdx.x >= d) ? s[threadIdx.x - d] : 0;
        __syncthreads();
        s[threadIdx.x] += t;
        __syncthreads();
    }
    if (threadIdx.x < nb) bsum[threadIdx.x] = s[threadIdx.x] - v;  // exclusive
}
__global__ void csr_scan3(int* __restrict__ off, const int* __restrict__ bsum, int n) {
    int g = blockIdx.x * 1024 + threadIdx.x;
    if (g < n) off[g + 1] += bsum[blockIdx.x];
    if (g == 0) off[0] = 0;
}
__global__ void csr_fill(const int* __restrict__ src, const int* __restrict__ dst,
                         const int* __restrict__ off, int* __restrict__ cnt,
                         int* __restrict__ csrc, int E) {
    int i = blockIdx.x * blockDim.x + threadIdx.x;
    if (i < E) {
        int d = dst[i];
        int p = off[d] + atomicAdd(&cnt[d], 1);
        csrc[p] = src[i];
    }
}

// ---------------- fused mean-aggregate: out = h + mean_in(h) ------------------
__global__ void aggregate_kernel(const float* __restrict__ h, const int* __restrict__ off,
                                 const int* __restrict__ csrc, const float* __restrict__ invd,
                                 float* __restrict__ out, int N)
{
    int wid  = threadIdx.x >> 5;
    int lane = threadIdx.x & 31;
    int node = blockIdx.x * (blockDim.x >> 5) + wid;
    if (node >= N) return;
    int beg = off[node], end = off[node + 1];
    float4 acc = make_float4(0.f, 0.f, 0.f, 0.f);
    const float4* h4 = reinterpret_cast<const float4*>(h);
    int e = beg;
    for (; e + 1 < end; e += 2) {
        int s0 = __ldg(csrc + e), s1 = __ldg(csrc + e + 1);
        float4 v0 = __ldg(h4 + s0 * 32 + lane);
        float4 v1 = __ldg(h4 + s1 * 32 + lane);
        acc.x += v0.x + v1.x; acc.y += v0.y + v1.y;
        acc.z += v0.z + v1.z; acc.w += v0.w + v1.w;
    }
    if (e < end) {
        int s0 = __ldg(csrc + e);
        float4 v0 = __ldg(h4 + s0 * 32 + lane);
        acc.x += v0.x; acc.y += v0.y; acc.z += v0.z; acc.w += v0.w;
    }
    float iv = invd[node];
    float4 b = __ldg(h4 + node * 32 + lane);
    reinterpret_cast<float4*>(out)[node * 32 + lane] =
        make_float4(b.x + acc.x * iv, b.y + acc.y * iv,
                    b.z + acc.z * iv, b.w + acc.w * iv);
}

// ---------------- launch -----------------------------------------------------
extern "C" void kernel_launch(void* const* d_in, const int* in_sizes, int n_in,
                              void* d_out, int out_size)
{
    const float* x   = (const float*)d_in[0];
    const int*   src = (const int*)  d_in[1];
    const int*   dst = (const int*)  d_in[2];
    const float* W1  = (const float*)d_in[3];
    const float* b1  = (const float*)d_in[4];
    const float* W2  = (const float*)d_in[5];
    const float* b2  = (const float*)d_in[6];
    const float* W3  = (const float*)d_in[7];
    const float* b3  = (const float*)d_in[8];
    const float* Wo1 = (const float*)d_in[9];
    const float* bo1 = (const float*)d_in[10];
    const float* Wo2 = (const float*)d_in[11];
    const float* bo2 = (const float*)d_in[12];
    float* out = (float*)d_out;

    const int N = in_sizes[0] / FD;    // 100000
    const int E = in_sizes[1];         // 800000

    float *bufA, *bufB, *invd;
    int *deg, *off, *cnt, *bsum, *csrc;
    cudaGetSymbolAddress((void**)&bufA, g_bufA);
    cudaGetSymbolAddress((void**)&bufB, g_bufB);
    cudaGetSymbolAddress((void**)&invd, g_invdeg);
    cudaGetSymbolAddress((void**)&deg,  g_deg);
    cudaGetSymbolAddress((void**)&off,  g_off);
    cudaGetSymbolAddress((void**)&cnt,  g_cnt);
    cudaGetSymbolAddress((void**)&bsum, g_bsum);
    cudaGetSymbolAddress((void**)&csrc, g_csrc);

    const int smemG   = 2 * (64 + 128) * 136 * 2;          // 104448 (standalone)
    const int smemF128 = 6 * 128 * 136 * 2;                 // 208896 (fused, NOUT2=128)
    const int smemF64  = (4 * 128 + 2 * 64) * 136 * 2;      // 174080 (fused, NOUT2=64)
    cudaFuncSetAttribute(gemm_mma<128, true>, cudaFuncAttributeMaxDynamicSharedMemorySize, smemG);
    cudaFuncSetAttribute(gemm_fused2<128, false>, cudaFuncAttributeMaxDynamicSharedMemorySize, smemF128);
    cudaFuncSetAttribute(gemm_fused2<64,  false>, cudaFuncAttributeMaxDynamicSharedMemorySize, smemF64);

    const int gb  = (N + 63) / 64;                // 1563 (standalone, 64-row tiles)
    const int gb2 = (N + 127) / 128;              // 782  (fused, 128-row tiles)
    const int nb  = (N + 1023) / 1024;            // 98 scan blocks
    const int ag  = (N + 7) / 8;                  // aggregate: 8 warps/block

    // ---- CSR build (once per call; reused by both aggregations) ----
    zero_int_kernel<<<(N + 255) / 256, 256>>>(deg, N);
    hist_kernel<<<(E + 255) / 256, 256>>>(dst, E, deg);
    csr_scan1<<<nb, 1024>>>(deg, off, bsum, invd, cnt, N);
    csr_scan2<<<1, 128>>>(bsum, nb);
    csr_scan3<<<nb, 1024>>>(off, bsum, N);
    csr_fill<<<(E + 255) / 256, 256>>>(src, dst, off, cnt, csrc, E);

    // x2 = lin(relu(lin(x,W1,b1)),W2,b2)        [fused]
    gemm_fused2<128, false><<<gb2, 512, smemF128>>>(x, W1, b1, W2, b2, bufA, N);

    // h = x2 + mean_agg(x2)
    aggregate_kernel<<<ag, 256>>>(bufA, off, csrc, invd, bufB, N);

    // h = lin(relu(lin(h,W1,b1)),W2,b2)          [fused]
    gemm_fused2<128, false><<<gb2, 512, smemF128>>>(bufB, W1, b1, W2, b2, bufA, N);

    // h = relu(lin(h,W3,b3))
    gemm_mma<128, true><<<gb, 256, smemG>>>(bufA, W3, b3, bufB, N);

    // h = h + mean_agg(h)
    aggregate_kernel<<<ag, 256>>>(bufB, off, csrc, invd, bufA, N);

    // h = relu(lin(h,W3,b3))
    gemm_mma<128, true><<<gb, 256, smemG>>>(bufA, W3, b3, bufB, N);

    // h = relu(lin(h,Wo1,bo1)); out = lin(h,Wo2,bo2)   [fused]
    gemm_fused2<64, false><<<gb2, 512, smemF64>>>(bufB, Wo1, bo1, Wo2, bo2, out, N);
}

// round 10
// speedup vs baseline: 5.2631x; 1.0454x over previous
#include <cuda_runtime.h>
#include <cstdint>

#define NN 100000
#define EE 800000
#define FD 128

// ---------------- scratch (device globals; no allocations allowed) ----------
__device__ float g_bufA[NN * FD];
__device__ float g_bufB[NN * FD];
__device__ float g_invdeg[NN];
__device__ int   g_deg[NN];
__device__ int   g_off[NN + 1];
__device__ int   g_cnt[NN];
__device__ int   g_bsum[128];
__device__ int   g_csrc[EE];

// ---------------- helpers ----------------------------------------------------
#define LDSM4(q, addr)                                                        \
    asm volatile("ldmatrix.sync.aligned.m8n8.x4.shared.b16 {%0,%1,%2,%3}, [%4];" \
        : "=r"((q)[0]), "=r"((q)[1]), "=r"((q)[2]), "=r"((q)[3]) : "r"(addr))

__device__ __forceinline__ uint32_t packbf(float hi, float lo) {
    uint32_t d;
    asm("cvt.rn.bf16x2.f32 %0, %1, %2;" : "=r"(d) : "f"(hi), "f"(lo));
    return d;
}

// A frags from our ldmatrix pattern: {q0,q2,q1,q3} order for mma
#define MMA_BF16(d, a, b0, b1)                                                \
    asm volatile(                                                             \
        "mma.sync.aligned.m16n8k16.row.col.f32.bf16.bf16.f32 "                \
        "{%0,%1,%2,%3}, {%4,%5,%6,%7}, {%8,%9}, {%0,%1,%2,%3};"               \
        : "+f"((d)[0]), "+f"((d)[1]), "+f"((d)[2]), "+f"((d)[3])              \
        : "r"((a)[0]), "r"((a)[2]), "r"((a)[1]), "r"((a)[3]),                 \
          "r"(b0), "r"(b1))

__device__ __forceinline__ void split4(float4 v, uint32_t& p01, uint32_t& p23,
                                       uint32_t& l01, uint32_t& l23) {
    p01 = packbf(v.y, v.x);
    p23 = packbf(v.w, v.z);
    float hx = __uint_as_float(p01 << 16), hy = __uint_as_float(p01 & 0xFFFF0000u);
    float hz = __uint_as_float(p23 << 16), hw = __uint_as_float(p23 & 0xFFFF0000u);
    l01 = packbf(v.y - hy, v.x - hx);
    l23 = packbf(v.w - hw, v.z - hz);
}

constexpr int LDH = 136, LDU = 68;
constexpr uint32_t ROWB = 272;

// ---------------- shared bf16 3-pass mainloop (K=128, 8 k16 steps) -----------
template<int NT>
__device__ __forceinline__ void bf16_mainloop(
    uint32_t aBH0, uint32_t aBH1, uint32_t aBL0, uint32_t aBL1,
    const uint32_t* bBH, const uint32_t* bBL, float (*acc)[4])
{
    constexpr int NI = NT * 2;
    uint32_t aH[2][2][4], aL[2][2][4], bH[2][NT][4], bL[2][NT][4];
    LDSM4(aH[0][0], aBH0); LDSM4(aH[0][1], aBH1);
    LDSM4(aL[0][0], aBL0); LDSM4(aL[0][1], aBL1);
    #pragma unroll
    for (int t = 0; t < NT; ++t) { LDSM4(bH[0][t], bBH[t]); LDSM4(bL[0][t], bBL[t]); }

    #pragma unroll
    for (int ks = 0; ks < 8; ++ks) {
        const int cur = ks & 1, nxt = cur ^ 1;
        if (ks < 7) {
            const uint32_t ko = (uint32_t)(ks + 1) * 32u;
            LDSM4(aH[nxt][0], aBH0 + ko); LDSM4(aH[nxt][1], aBH1 + ko);
            LDSM4(aL[nxt][0], aBL0 + ko); LDSM4(aL[nxt][1], aBL1 + ko);
            #pragma unroll
            for (int t = 0; t < NT; ++t) {
                LDSM4(bH[nxt][t], bBH[t] + ko);
                LDSM4(bL[nxt][t], bBL[t] + ko);
            }
        }
        #pragma unroll
        for (int mi = 0; mi < 2; ++mi)
            #pragma unroll
            for (int t = 0; t < NT; ++t) {
                MMA_BF16(acc[mi * NI + t * 2 + 0], aH[cur][mi], bH[cur][t][0], bH[cur][t][1]);
                MMA_BF16(acc[mi * NI + t * 2 + 1], aH[cur][mi], bH[cur][t][2], bH[cur][t][3]);
            }
        #pragma unroll
        for (int mi = 0; mi < 2; ++mi)
            #pragma unroll
            for (int t = 0; t < NT; ++t) {
                MMA_BF16(acc[mi * NI + t * 2 + 0], aH[cur][mi], bL[cur][t][0], bL[cur][t][1]);
                MMA_BF16(acc[mi * NI + t * 2 + 1], aH[cur][mi], bL[cur][t][2], bL[cur][t][3]);
            }
        #pragma unroll
        for (int mi = 0; mi < 2; ++mi)
            #pragma unroll
            for (int t = 0; t < NT; ++t) {
                MMA_BF16(acc[mi * NI + t * 2 + 0], aL[cur][mi], bH[cur][t][0], bH[cur][t][1]);
                MMA_BF16(acc[mi * NI + t * 2 + 1], aL[cur][mi], bH[cur][t][2], bH[cur][t][3]);
            }
    }
}

// stage a [ROWS x 128] fp32 weight matrix into bf16 hi/lo planes (512 threads)
template<int ROWS>
__device__ __forceinline__ void stage_w(const float* __restrict__ W,
                                        uint32_t* Wh, uint32_t* Wl, int tid)
{
    #pragma unroll
    for (int it = 0; it < ROWS / 16; ++it) {
        int idx = tid + it * 512;
        int r = idx >> 5, c4 = idx & 31;
        float4 v = reinterpret_cast<const float4*>(W)[(size_t)r * 32 + c4];
        uint32_t p01, p23, l01, l23;
        split4(v, p01, p23, l01, l23);
        int o = r * LDU + c4 * 2;
        Wh[o] = p01; Wh[o + 1] = p23;
        Wl[o] = l01; Wl[o + 1] = l23;
    }
}

// epilogue -> mid planes: bias + optional relu, split to bf16 hi/lo in A planes
template<bool RELU>
__device__ __forceinline__ void write_mid(const float (*acc)[4], const float* bias,
                                          int wm, int wn, int qr, int qc,
                                          uint32_t* AhiU, uint32_t* AloU)
{
    const int cb = wn * 32 + qc * 2;
    #pragma unroll
    for (int ni = 0; ni < 4; ++ni) {
        int c = cb + ni * 8;
        float bb0 = __ldg(bias + c), bb1 = __ldg(bias + c + 1);
        #pragma unroll
        for (int mi = 0; mi < 2; ++mi) {
            const float* a = acc[mi * 4 + ni];
            float v0 = a[0] + bb0, v1 = a[1] + bb1, v2 = a[2] + bb0, v3 = a[3] + bb1;
            if (RELU) {
                v0 = fmaxf(v0, 0.f); v1 = fmaxf(v1, 0.f);
                v2 = fmaxf(v2, 0.f); v3 = fmaxf(v3, 0.f);
            }
            int r = wm * 32 + mi * 16 + qr;
            uint32_t p = packbf(v1, v0);
            float h0 = __uint_as_float(p << 16), h1 = __uint_as_float(p & 0xFFFF0000u);
            uint32_t l = packbf(v1 - h1, v0 - h0);
            int o = r * LDU + (c >> 1);
            AhiU[o] = p; AloU[o] = l;
            p = packbf(v3, v2);
            h0 = __uint_as_float(p << 16); h1 = __uint_as_float(p & 0xFFFF0000u);
            l = packbf(v3 - h1, v2 - h0);
            o += 8 * LDU;
            AhiU[o] = p; AloU[o] = l;
        }
    }
}

// ---------------- fused 2-layer GEMM: out = lin(relu(lin(A,W1,b1)),W2,b2) -----
__global__ void __launch_bounds__(512)
gemm_fused2(const float* __restrict__ A, const float* __restrict__ W1,
            const float* __restrict__ b1, const float* __restrict__ W2,
            const float* __restrict__ b2, float* __restrict__ out, int N)
{
    constexpr int PA = 128 * LDU;
    extern __shared__ uint16_t smh[];
    uint32_t* U    = reinterpret_cast<uint32_t*>(smh);
    uint32_t* AhiU = U;
    uint32_t* AloU = U + PA;
    uint32_t* B1h  = U + 2 * PA;
    uint32_t* B1l  = U + 3 * PA;
    uint32_t* B2h  = U + 4 * PA;
    uint32_t* B2l  = U + 5 * PA;

    const int tid  = threadIdx.x;
    const int wid  = tid >> 5;
    const int lane = tid & 31;
    const int wm   = wid & 3;
    const int wn   = wid >> 2;
    const int row0 = blockIdx.x * 128;
    const int qr   = lane >> 2;
    const int qc   = lane & 3;

    #pragma unroll
    for (int it = 0; it < 8; ++it) {
        int idx = tid + it * 512;
        int r = idx >> 5, c4 = idx & 31;
        int row = row0 + r;
        float4 v = make_float4(0.f, 0.f, 0.f, 0.f);
        if (row < N) v = reinterpret_cast<const float4*>(A)[(size_t)row * 32 + c4];
        uint32_t p01, p23, l01, l23;
        split4(v, p01, p23, l01, l23);
        int o = r * LDU + c4 * 2;
        AhiU[o] = p01; AhiU[o + 1] = p23;
        AloU[o] = l01; AloU[o + 1] = l23;
    }
    stage_w<128>(W1, B1h, B1l, tid);
    stage_w<128>(W2, B2h, B2l, tid);
    __syncthreads();

    uint32_t sb;
    asm("{ .reg .u64 t; cvta.to.shared.u64 t, %1; cvt.u32.u64 %0, t; }" : "=r"(sb) : "l"(smh));
    const int m  = lane >> 3;
    const int mr = ((m >> 1) << 3) + (lane & 7);
    const uint32_t mc = (uint32_t)(m & 1) * 16u;
    const uint32_t oAlo = (uint32_t)PA * 4u;
    const uint32_t aBH0 = sb + (uint32_t)(wm * 32 + 0  + mr) * ROWB + mc;
    const uint32_t aBH1 = sb + (uint32_t)(wm * 32 + 16 + mr) * ROWB + mc;

    uint32_t bB[2], bL[2];
    #pragma unroll
    for (int t = 0; t < 2; ++t) {
        bB[t] = sb + (uint32_t)(2 * PA) * 4u + (uint32_t)(wn * 32 + t * 16 + mr) * ROWB + mc;
        bL[t] = bB[t] + oAlo;
    }
    {
        float acc[8][4];
        #pragma unroll
        for (int i = 0; i < 8; ++i)
            #pragma unroll
            for (int c = 0; c < 4; ++c) acc[i][c] = 0.f;
        bf16_mainloop<2>(aBH0, aBH1, aBH0 + oAlo, aBH1 + oAlo, bB, bL, acc);
        __syncthreads();
        write_mid<true>(acc, b1, wm, wn, qr, qc, AhiU, AloU);
    }
    __syncthreads();

    float acc2[8][4];
    #pragma unroll
    for (int i = 0; i < 8; ++i)
        #pragma unroll
        for (int c = 0; c < 4; ++c) acc2[i][c] = 0.f;
    #pragma unroll
    for (int t = 0; t < 2; ++t) {
        bB[t] = sb + (uint32_t)(4 * PA) * 4u + (uint32_t)(wn * 32 + t * 16 + mr) * ROWB + mc;
        bL[t] = bB[t] + oAlo;
    }
    bf16_mainloop<2>(aBH0, aBH1, aBH0 + oAlo, aBH1 + oAlo, bB, bL, acc2);

    const int rbase = row0 + wm * 32 + qr;
    const int cbase = wn * 32 + qc * 2;
    #pragma unroll
    for (int ni = 0; ni < 4; ++ni) {
        int c = cbase + ni * 8;
        float b0 = __ldg(b2 + c), b1v = __ldg(b2 + c + 1);
        #pragma unroll
        for (int mi = 0; mi < 2; ++mi) {
            const float* a = acc2[mi * 4 + ni];
            int r = rbase + mi * 16;
            if (r < N)
                *reinterpret_cast<float2*>(out + (size_t)r * 128 + c) =
                    make_float2(a[0] + b0, a[1] + b1v);
            if (r + 8 < N)
                *reinterpret_cast<float2*>(out + (size_t)(r + 8) * 128 + c) =
                    make_float2(a[2] + b0, a[3] + b1v);
        }
    }
}

// ---------------- fused 3-layer GEMM -------------------------------------------
// L1: relu(lin(A,W1,b1));  L2: lin(.,W2,b2) [+relu if R2];  L3: lin(.,W3,b3) [+relu if R3]
// W3 restaged into W1's smem slot after GEMM1.
template<bool R2, int NOUT3, bool R3>
__global__ void __launch_bounds__(512)
gemm_fused3(const float* __restrict__ A,
            const float* __restrict__ W1, const float* __restrict__ b1,
            const float* __restrict__ W2, const float* __restrict__ b2,
            const float* __restrict__ W3, const float* __restrict__ b3,
            float* __restrict__ out, int N)
{
    constexpr int PA = 128 * LDU;
    extern __shared__ uint16_t smh[];
    uint32_t* U    = reinterpret_cast<uint32_t*>(smh);
    uint32_t* AhiU = U;
    uint32_t* AloU = U + PA;
    uint32_t* B1h  = U + 2 * PA;     // W1, later W3
    uint32_t* B1l  = U + 3 * PA;
    uint32_t* B2h  = U + 4 * PA;
    uint32_t* B2l  = U + 5 * PA;

    const int tid  = threadIdx.x;
    const int wid  = tid >> 5;
    const int lane = tid & 31;
    const int wm   = wid & 3;
    const int wn   = wid >> 2;
    const int row0 = blockIdx.x * 128;
    const int qr   = lane >> 2;
    const int qc   = lane & 3;

    #pragma unroll
    for (int it = 0; it < 8; ++it) {
        int idx = tid + it * 512;
        int r = idx >> 5, c4 = idx & 31;
        int row = row0 + r;
        float4 v = make_float4(0.f, 0.f, 0.f, 0.f);
        if (row < N) v = reinterpret_cast<const float4*>(A)[(size_t)row * 32 + c4];
        uint32_t p01, p23, l01, l23;
        split4(v, p01, p23, l01, l23);
        int o = r * LDU + c4 * 2;
        AhiU[o] = p01; AhiU[o + 1] = p23;
        AloU[o] = l01; AloU[o + 1] = l23;
    }
    stage_w<128>(W1, B1h, B1l, tid);
    stage_w<128>(W2, B2h, B2l, tid);
    __syncthreads();

    uint32_t sb;
    asm("{ .reg .u64 t; cvta.to.shared.u64 t, %1; cvt.u32.u64 %0, t; }" : "=r"(sb) : "l"(smh));
    const int m  = lane >> 3;
    const int mr = ((m >> 1) << 3) + (lane & 7);
    const uint32_t mc = (uint32_t)(m & 1) * 16u;
    const uint32_t oAlo = (uint32_t)PA * 4u;
    const uint32_t aBH0 = sb + (uint32_t)(wm * 32 + 0  + mr) * ROWB + mc;
    const uint32_t aBH1 = sb + (uint32_t)(wm * 32 + 16 + mr) * ROWB + mc;
    const uint32_t oB1 = (uint32_t)(2 * PA) * 4u;
    const uint32_t oB2 = (uint32_t)(4 * PA) * 4u;

    // ---- GEMM1 (W1, relu) ----
    {
        float acc[8][4];
        #pragma unroll
        for (int i = 0; i < 8; ++i)
            #pragma unroll
            for (int c = 0; c < 4; ++c) acc[i][c] = 0.f;
        uint32_t bB[2], bL[2];
        #pragma unroll
        for (int t = 0; t < 2; ++t) {
            bB[t] = sb + oB1 + (uint32_t)(wn * 32 + t * 16 + mr) * ROWB + mc;
            bL[t] = bB[t] + oAlo;
        }
        bf16_mainloop<2>(aBH0, aBH1, aBH0 + oAlo, aBH1 + oAlo, bB, bL, acc);
        __syncthreads();                       // A + W1 reads done
        write_mid<true>(acc, b1, wm, wn, qr, qc, AhiU, AloU);
        stage_w<NOUT3>(W3, B1h, B1l, tid);     // restage W3 over W1
    }
    __syncthreads();

    // ---- GEMM2 (W2, R2) ----
    {
        float acc[8][4];
        #pragma unroll
        for (int i = 0; i < 8; ++i)
            #pragma unroll
            for (int c = 0; c < 4; ++c) acc[i][c] = 0.f;
        uint32_t bB[2], bL[2];
        #pragma unroll
        for (int t = 0; t < 2; ++t) {
            bB[t] = sb + oB2 + (uint32_t)(wn * 32 + t * 16 + mr) * ROWB + mc;
            bL[t] = bB[t] + oAlo;
        }
        bf16_mainloop<2>(aBH0, aBH1, aBH0 + oAlo, aBH1 + oAlo, bB, bL, acc);
        __syncthreads();                       // mid1 reads done
        write_mid<R2>(acc, b2, wm, wn, qr, qc, AhiU, AloU);
    }
    __syncthreads();

    // ---- GEMM3 (W3, NOUT3, R3) ----
    constexpr int NC3 = NOUT3 / 4;
    constexpr int NT3 = NC3 / 16;
    constexpr int NI3 = NT3 * 2;
    float acc3[2 * NI3][4];
    #pragma unroll
    for (int i = 0; i < 2 * NI3; ++i)
        #pragma unroll
        for (int c = 0; c < 4; ++c) acc3[i][c] = 0.f;
    uint32_t bB3[NT3], bL3[NT3];
    #pragma unroll
    for (int t = 0; t < NT3; ++t) {
        bB3[t] = sb + oB1 + (uint32_t)(wn * NC3 + t * 16 + mr) * ROWB + mc;
        bL3[t] = bB3[t] + oAlo;
    }
    bf16_mainloop<NT3>(aBH0, aBH1, aBH0 + oAlo, aBH1 + oAlo, bB3, bL3, acc3);

    const int rbase = row0 + wm * 32 + qr;
    const int cbase = wn * NC3 + qc * 2;
    #pragma unroll
    for (int ni = 0; ni < NI3; ++ni) {
        int c = cbase + ni * 8;
        float b0 = __ldg(b3 + c), b1v = __ldg(b3 + c + 1);
        #pragma unroll
        for (int mi = 0; mi < 2; ++mi) {
            const float* a = acc3[mi * NI3 + ni];
            int r = rbase + mi * 16;
            float v0 = a[0] + b0, v1 = a[1] + b1v, v2 = a[2] + b0, v3 = a[3] + b1v;
            if (R3) {
                v0 = fmaxf(v0, 0.f); v1 = fmaxf(v1, 0.f);
                v2 = fmaxf(v2, 0.f); v3 = fmaxf(v3, 0.f);
            }
            if (r < N)
                *reinterpret_cast<float2*>(out + (size_t)r * NOUT3 + c) = make_float2(v0, v1);
            if (r + 8 < N)
                *reinterpret_cast<float2*>(out + (size_t)(r + 8) * NOUT3 + c) = make_float2(v2, v3);
        }
    }
}

// ---------------- CSR build ---------------------------------------------------
__global__ void zero_int_kernel(int* p, int n) {
    int i = blockIdx.x * blockDim.x + threadIdx.x;
    if (i < n) p[i] = 0;
}
__global__ void hist_kernel(const int* __restrict__ dst, int E, int* __restrict__ deg) {
    int i = blockIdx.x * blockDim.x + threadIdx.x;
    if (i < E) atomicAdd(&deg[dst[i]], 1);
}
__global__ void csr_scan1(const int* __restrict__ deg, int* __restrict__ off,
                          int* __restrict__ bsum, float* __restrict__ invd,
                          int* __restrict__ cnt, int n) {
    __shared__ int s[1024];
    int g = blockIdx.x * 1024 + threadIdx.x;
    int v = (g < n) ? deg[g] : 0;
    if (g < n) { invd[g] = 1.0f / fmaxf((float)v, 1.0f); cnt[g] = 0; }
    s[threadIdx.x] = v;
    __syncthreads();
    #pragma unroll
    for (int d = 1; d < 1024; d <<= 1) {
        int t = (threadIdx.x >= d) ? s[threadIdx.x - d] : 0;
        __syncthreads();
        s[threadIdx.x] += t;
        __syncthreads();
    }
    if (g < n) off[g + 1] = s[threadIdx.x];
    if (threadIdx.x == 1023) bsum[blockIdx.x] = s[1023];
}
__global__ void csr_scan2(int* bsum, int nb) {
    __shared__ int s[128];
    int v = (threadIdx.x < nb) ? bsum[threadIdx.x] : 0;
    s[threadIdx.x] = v;
    __syncthreads();
    #pragma unroll
    for (int d = 1; d < 128; d <<= 1) {
        int t = (threadIdx.x >= d) ? s[threadIdx.x - d] : 0;
        __syncthreads();
        s[threadIdx.x] += t;
        __syncthreads();
    }
    if (threadIdx.x < nb) bsum[threadIdx.x] = s[threadIdx.x] - v;  // exclusive
}
__global__ void csr_scan3(int* __restrict__ off, const int* __restrict__ bsum, int n) {
    int g = blockIdx.x * 1024 + threadIdx.x;
    if (g < n) off[g + 1] += bsum[blockIdx.x];
    if (g == 0) off[0] = 0;
}
__global__ void csr_fill(const int* __restrict__ src, const int* __restrict__ dst,
                         const int* __restrict__ off, int* __restrict__ cnt,
                         int* __restrict__ csrc, int E) {
    int i = blockIdx.x * blockDim.x + threadIdx.x;
    if (i < E) {
        int d = dst[i];
        int p = off[d] + atomicAdd(&cnt[d], 1);
        csrc[p] = src[i];
    }
}

// ---------------- fused mean-aggregate: out = h + mean_in(h) ------------------
__global__ void aggregate_kernel(const float* __restrict__ h, const int* __restrict__ off,
                                 const int* __restrict__ csrc, const float* __restrict__ invd,
                                 float* __restrict__ out, int N)
{
    int wid  = threadIdx.x >> 5;
    int lane = threadIdx.x & 31;
    int node = blockIdx.x * (blockDim.x >> 5) + wid;
    if (node >= N) return;
    int beg = off[node], end = off[node + 1];
    float4 acc = make_float4(0.f, 0.f, 0.f, 0.f);
    const float4* h4 = reinterpret_cast<const float4*>(h);
    int e = beg;
    for (; e + 1 < end; e += 2) {
        int s0 = __ldg(csrc + e), s1 = __ldg(csrc + e + 1);
        float4 v0 = __ldg(h4 + s0 * 32 + lane);
        float4 v1 = __ldg(h4 + s1 * 32 + lane);
        acc.x += v0.x + v1.x; acc.y += v0.y + v1.y;
        acc.z += v0.z + v1.z; acc.w += v0.w + v1.w;
    }
    if (e < end) {
        int s0 = __ldg(csrc + e);
        float4 v0 = __ldg(h4 + s0 * 32 + lane);
        acc.x += v0.x; acc.y += v0.y; acc.z += v0.z; acc.w += v0.w;
    }
    float iv = invd[node];
    float4 b = __ldg(h4 + node * 32 + lane);
    reinterpret_cast<float4*>(out)[node * 32 + lane] =
        make_float4(b.x + acc.x * iv, b.y + acc.y * iv,
                    b.z + acc.z * iv, b.w + acc.w * iv);
}

// ---------------- launch -----------------------------------------------------
extern "C" void kernel_launch(void* const* d_in, const int* in_sizes, int n_in,
                              void* d_out, int out_size)
{
    const float* x   = (const float*)d_in[0];
    const int*   src = (const int*)  d_in[1];
    const int*   dst = (const int*)  d_in[2];
    const float* W1  = (const float*)d_in[3];
    const float* b1  = (const float*)d_in[4];
    const float* W2  = (const float*)d_in[5];
    const float* b2  = (const float*)d_in[6];
    const float* W3  = (const float*)d_in[7];
    const float* b3  = (const float*)d_in[8];
    const float* Wo1 = (const float*)d_in[9];
    const float* bo1 = (const float*)d_in[10];
    const float* Wo2 = (const float*)d_in[11];
    const float* bo2 = (const float*)d_in[12];
    float* out = (float*)d_out;

    const int N = in_sizes[0] / FD;    // 100000
    const int E = in_sizes[1];         // 800000

    float *bufA, *bufB, *invd;
    int *deg, *off, *cnt, *bsum, *csrc;
    cudaGetSymbolAddress((void**)&bufA, g_bufA);
    cudaGetSymbolAddress((void**)&bufB, g_bufB);
    cudaGetSymbolAddress((void**)&invd, g_invdeg);
    cudaGetSymbolAddress((void**)&deg,  g_deg);
    cudaGetSymbolAddress((void**)&off,  g_off);
    cudaGetSymbolAddress((void**)&cnt,  g_cnt);
    cudaGetSymbolAddress((void**)&bsum, g_bsum);
    cudaGetSymbolAddress((void**)&csrc, g_csrc);

    const int smemF = 6 * 128 * 136 * 2;                  // 208896
    cudaFuncSetAttribute(gemm_fused2, cudaFuncAttributeMaxDynamicSharedMemorySize, smemF);
    cudaFuncSetAttribute(gemm_fused3<false, 128, true>, cudaFuncAttributeMaxDynamicSharedMemorySize, smemF);
    cudaFuncSetAttribute(gemm_fused3<true,  64,  false>, cudaFuncAttributeMaxDynamicSharedMemorySize, smemF);

    const int gb2 = (N + 127) / 128;              // 782 (128-row tiles)
    const int nb  = (N + 1023) / 1024;            // 98 scan blocks
    const int ag  = (N + 7) / 8;                  // aggregate: 8 warps/block

    // ---- CSR build (once per call; reused by both aggregations) ----
    zero_int_kernel<<<(N + 255) / 256, 256>>>(deg, N);
    hist_kernel<<<(E + 255) / 256, 256>>>(dst, E, deg);
    csr_scan1<<<nb, 1024>>>(deg, off, bsum, invd, cnt, N);
    csr_scan2<<<1, 128>>>(bsum, nb);
    csr_scan3<<<nb, 1024>>>(off, bsum, N);
    csr_fill<<<(E + 255) / 256, 256>>>(src, dst, off, cnt, csrc, E);

    // x2 = lin(relu(lin(x,W1,b1)),W2,b2)
    gemm_fused2<<<gb2, 512, smemF>>>(x, W1, b1, W2, b2, bufA, N);

    // h = x2 + mean_agg(x2)
    aggregate_kernel<<<ag, 256>>>(bufA, off, csrc, invd, bufB, N);

    // h = relu(lin( lin(relu(lin(h,W1,b1)),W2,b2), W3,b3))
    gemm_fused3<false, 128, true><<<gb2, 512, smemF>>>(bufB, W1, b1, W2, b2, W3, b3, bufA, N);

    // h = h + mean_agg(h)
    aggregate_kernel<<<ag, 256>>>(bufA, off, csrc, invd, bufB, N);

    // out = lin( relu(lin( relu(lin(h,W3,b3)), Wo1,bo1)), Wo2,bo2)
    gemm_fused3<true, 64, false><<<gb2, 512, smemF>>>(bufB, W3, b3, Wo1, bo1, Wo2, bo2, out, N);
}

// round 11
// speedup vs baseline: 5.3259x; 1.0119x over previous
#include <cuda_runtime.h>
#include <cstdint>

#define NN 100000
#define EE 800000
#define FD 128

// ---------------- scratch (device globals; no allocations allowed) ----------
__device__ float g_bufA[NN * FD];
__device__ float g_bufB[NN * FD];
__device__ float g_invdeg[NN];
__device__ int   g_deg[NN];
__device__ int   g_off[NN + 1];
__device__ int   g_cnt[NN];
__device__ int   g_bsum[128];
__device__ int   g_csrc[EE];

// ---------------- helpers ----------------------------------------------------
#define LDSM4(q, addr)                                                        \
    asm volatile("ldmatrix.sync.aligned.m8n8.x4.shared.b16 {%0,%1,%2,%3}, [%4];" \
        : "=r"((q)[0]), "=r"((q)[1]), "=r"((q)[2]), "=r"((q)[3]) : "r"(addr))

__device__ __forceinline__ uint32_t packbf(float hi, float lo) {
    uint32_t d;
    asm("cvt.rn.bf16x2.f32 %0, %1, %2;" : "=r"(d) : "f"(hi), "f"(lo));
    return d;
}

// A frags from our ldmatrix pattern: {q0,q2,q1,q3} order for mma
#define MMA_BF16(d, a, b0, b1)                                                \
    asm volatile(                                                             \
        "mma.sync.aligned.m16n8k16.row.col.f32.bf16.bf16.f32 "                \
        "{%0,%1,%2,%3}, {%4,%5,%6,%7}, {%8,%9}, {%0,%1,%2,%3};"               \
        : "+f"((d)[0]), "+f"((d)[1]), "+f"((d)[2]), "+f"((d)[3])              \
        : "r"((a)[0]), "r"((a)[2]), "r"((a)[1]), "r"((a)[3]),                 \
          "r"(b0), "r"(b1))

__device__ __forceinline__ void split4(float4 v, uint32_t& p01, uint32_t& p23,
                                       uint32_t& l01, uint32_t& l23) {
    p01 = packbf(v.y, v.x);
    p23 = packbf(v.w, v.z);
    float hx = __uint_as_float(p01 << 16), hy = __uint_as_float(p01 & 0xFFFF0000u);
    float hz = __uint_as_float(p23 << 16), hw = __uint_as_float(p23 & 0xFFFF0000u);
    l01 = packbf(v.y - hy, v.x - hx);
    l23 = packbf(v.w - hw, v.z - hz);
}

constexpr int LDH = 136, LDU = 68;
constexpr uint32_t ROWB = 272;

// ---------------- shared bf16 3-pass mainloop (K=128, 8 k16 steps) -----------
template<int NT>
__device__ __forceinline__ void bf16_mainloop(
    uint32_t aBH0, uint32_t aBH1, uint32_t aBL0, uint32_t aBL1,
    const uint32_t* bBH, const uint32_t* bBL, float (*acc)[4])
{
    constexpr int NI = NT * 2;
    uint32_t aH[2][2][4], aL[2][2][4], bH[2][NT][4], bL[2][NT][4];
    LDSM4(aH[0][0], aBH0); LDSM4(aH[0][1], aBH1);
    LDSM4(aL[0][0], aBL0); LDSM4(aL[0][1], aBL1);
    #pragma unroll
    for (int t = 0; t < NT; ++t) { LDSM4(bH[0][t], bBH[t]); LDSM4(bL[0][t], bBL[t]); }

    #pragma unroll
    for (int ks = 0; ks < 8; ++ks) {
        const int cur = ks & 1, nxt = cur ^ 1;
        if (ks < 7) {
            const uint32_t ko = (uint32_t)(ks + 1) * 32u;
            LDSM4(aH[nxt][0], aBH0 + ko); LDSM4(aH[nxt][1], aBH1 + ko);
            LDSM4(aL[nxt][0], aBL0 + ko); LDSM4(aL[nxt][1], aBL1 + ko);
            #pragma unroll
            for (int t = 0; t < NT; ++t) {
                LDSM4(bH[nxt][t], bBH[t] + ko);
                LDSM4(bL[nxt][t], bBL[t] + ko);
            }
        }
        #pragma unroll
        for (int mi = 0; mi < 2; ++mi)
            #pragma unroll
            for (int t = 0; t < NT; ++t) {
                MMA_BF16(acc[mi * NI + t * 2 + 0], aH[cur][mi], bH[cur][t][0], bH[cur][t][1]);
                MMA_BF16(acc[mi * NI + t * 2 + 1], aH[cur][mi], bH[cur][t][2], bH[cur][t][3]);
            }
        #pragma unroll
        for (int mi = 0; mi < 2; ++mi)
            #pragma unroll
            for (int t = 0; t < NT; ++t) {
                MMA_BF16(acc[mi * NI + t * 2 + 0], aH[cur][mi], bL[cur][t][0], bL[cur][t][1]);
                MMA_BF16(acc[mi * NI + t * 2 + 1], aH[cur][mi], bL[cur][t][2], bL[cur][t][3]);
            }
        #pragma unroll
        for (int mi = 0; mi < 2; ++mi)
            #pragma unroll
            for (int t = 0; t < NT; ++t) {
                MMA_BF16(acc[mi * NI + t * 2 + 0], aL[cur][mi], bH[cur][t][0], bH[cur][t][1]);
                MMA_BF16(acc[mi * NI + t * 2 + 1], aL[cur][mi], bH[cur][t][2], bH[cur][t][3]);
            }
    }
}

// stage a [ROWS x 128] fp32 weight matrix into bf16 hi/lo planes (512 threads)
template<int ROWS>
__device__ __forceinline__ void stage_w(const float* __restrict__ W,
                                        uint32_t* Wh, uint32_t* Wl, int tid)
{
    #pragma unroll
    for (int it = 0; it < ROWS / 16; ++it) {
        int idx = tid + it * 512;
        int r = idx >> 5, c4 = idx & 31;
        float4 v = reinterpret_cast<const float4*>(W)[(size_t)r * 32 + c4];
        uint32_t p01, p23, l01, l23;
        split4(v, p01, p23, l01, l23);
        int o = r * LDU + c4 * 2;
        Wh[o] = p01; Wh[o + 1] = p23;
        Wl[o] = l01; Wl[o + 1] = l23;
    }
}

// epilogue -> mid planes: bias + optional relu, split to bf16 hi/lo in A planes
template<bool RELU>
__device__ __forceinline__ void write_mid(const float (*acc)[4], const float* bias,
                                          int wm, int wn, int qr, int qc,
                                          uint32_t* AhiU, uint32_t* AloU)
{
    const int cb = wn * 32 + qc * 2;
    #pragma unroll
    for (int ni = 0; ni < 4; ++ni) {
        int c = cb + ni * 8;
        float bb0 = __ldg(bias + c), bb1 = __ldg(bias + c + 1);
        #pragma unroll
        for (int mi = 0; mi < 2; ++mi) {
            const float* a = acc[mi * 4 + ni];
            float v0 = a[0] + bb0, v1 = a[1] + bb1, v2 = a[2] + bb0, v3 = a[3] + bb1;
            if (RELU) {
                v0 = fmaxf(v0, 0.f); v1 = fmaxf(v1, 0.f);
                v2 = fmaxf(v2, 0.f); v3 = fmaxf(v3, 0.f);
            }
            int r = wm * 32 + mi * 16 + qr;
            uint32_t p = packbf(v1, v0);
            float h0 = __uint_as_float(p << 16), h1 = __uint_as_float(p & 0xFFFF0000u);
            uint32_t l = packbf(v1 - h1, v0 - h0);
            int o = r * LDU + (c >> 1);
            AhiU[o] = p; AloU[o] = l;
            p = packbf(v3, v2);
            h0 = __uint_as_float(p << 16); h1 = __uint_as_float(p & 0xFFFF0000u);
            l = packbf(v3 - h1, v2 - h0);
            o += 8 * LDU;
            AhiU[o] = p; AloU[o] = l;
        }
    }
}

// ---------------- fused 2-layer GEMM: out = lin(relu(lin(A,W1,b1)),W2,b2) -----
__global__ void __launch_bounds__(512)
gemm_fused2(const float* __restrict__ A, const float* __restrict__ W1,
            const float* __restrict__ b1, const float* __restrict__ W2,
            const float* __restrict__ b2, float* __restrict__ out, int N)
{
    constexpr int PA = 128 * LDU;
    extern __shared__ uint16_t smh[];
    uint32_t* U    = reinterpret_cast<uint32_t*>(smh);
    uint32_t* AhiU = U;
    uint32_t* AloU = U + PA;
    uint32_t* B1h  = U + 2 * PA;
    uint32_t* B1l  = U + 3 * PA;
    uint32_t* B2h  = U + 4 * PA;
    uint32_t* B2l  = U + 5 * PA;

    const int tid  = threadIdx.x;
    const int wid  = tid >> 5;
    const int lane = tid & 31;
    const int wm   = wid & 3;
    const int wn   = wid >> 2;
    const int row0 = blockIdx.x * 128;
    const int qr   = lane >> 2;
    const int qc   = lane & 3;

    #pragma unroll
    for (int it = 0; it < 8; ++it) {
        int idx = tid + it * 512;
        int r = idx >> 5, c4 = idx & 31;
        int row = row0 + r;
        float4 v = make_float4(0.f, 0.f, 0.f, 0.f);
        if (row < N) v = reinterpret_cast<const float4*>(A)[(size_t)row * 32 + c4];
        uint32_t p01, p23, l01, l23;
        split4(v, p01, p23, l01, l23);
        int o = r * LDU + c4 * 2;
        AhiU[o] = p01; AhiU[o + 1] = p23;
        AloU[o] = l01; AloU[o + 1] = l23;
    }
    stage_w<128>(W1, B1h, B1l, tid);
    stage_w<128>(W2, B2h, B2l, tid);
    __syncthreads();

    uint32_t sb;
    asm("{ .reg .u64 t; cvta.to.shared.u64 t, %1; cvt.u32.u64 %0, t; }" : "=r"(sb) : "l"(smh));
    const int m  = lane >> 3;
    const int mr = ((m >> 1) << 3) + (lane & 7);
    const uint32_t mc = (uint32_t)(m & 1) * 16u;
    const uint32_t oAlo = (uint32_t)PA * 4u;
    const uint32_t aBH0 = sb + (uint32_t)(wm * 32 + 0  + mr) * ROWB + mc;
    const uint32_t aBH1 = sb + (uint32_t)(wm * 32 + 16 + mr) * ROWB + mc;

    uint32_t bB[2], bL[2];
    #pragma unroll
    for (int t = 0; t < 2; ++t) {
        bB[t] = sb + (uint32_t)(2 * PA) * 4u + (uint32_t)(wn * 32 + t * 16 + mr) * ROWB + mc;
        bL[t] = bB[t] + oAlo;
    }
    {
        float acc[8][4];
        #pragma unroll
        for (int i = 0; i < 8; ++i)
            #pragma unroll
            for (int c = 0; c < 4; ++c) acc[i][c] = 0.f;
        bf16_mainloop<2>(aBH0, aBH1, aBH0 + oAlo, aBH1 + oAlo, bB, bL, acc);
        __syncthreads();
        write_mid<true>(acc, b1, wm, wn, qr, qc, AhiU, AloU);
    }
    __syncthreads();

    float acc2[8][4];
    #pragma unroll
    for (int i = 0; i < 8; ++i)
        #pragma unroll
        for (int c = 0; c < 4; ++c) acc2[i][c] = 0.f;
    #pragma unroll
    for (int t = 0; t < 2; ++t) {
        bB[t] = sb + (uint32_t)(4 * PA) * 4u + (uint32_t)(wn * 32 + t * 16 + mr) * ROWB + mc;
        bL[t] = bB[t] + oAlo;
    }
    bf16_mainloop<2>(aBH0, aBH1, aBH0 + oAlo, aBH1 + oAlo, bB, bL, acc2);

    const int rbase = row0 + wm * 32 + qr;
    const int cbase = wn * 32 + qc * 2;
    #pragma unroll
    for (int ni = 0; ni < 4; ++ni) {
        int c = cbase + ni * 8;
        float b0 = __ldg(b2 + c), b1v = __ldg(b2 + c + 1);
        #pragma unroll
        for (int mi = 0; mi < 2; ++mi) {
            const float* a = acc2[mi * 4 + ni];
            int r = rbase + mi * 16;
            if (r < N)
                *reinterpret_cast<float2*>(out + (size_t)r * 128 + c) =
                    make_float2(a[0] + b0, a[1] + b1v);
            if (r + 8 < N)
                *reinterpret_cast<float2*>(out + (size_t)(r + 8) * 128 + c) =
                    make_float2(a[2] + b0, a[3] + b1v);
        }
    }
}

// ---------------- fused 3-layer GEMM -------------------------------------------
template<bool R2, int NOUT3, bool R3>
__global__ void __launch_bounds__(512)
gemm_fused3(const float* __restrict__ A,
            const float* __restrict__ W1, const float* __restrict__ b1,
            const float* __restrict__ W2, const float* __restrict__ b2,
            const float* __restrict__ W3, const float* __restrict__ b3,
            float* __restrict__ out, int N)
{
    constexpr int PA = 128 * LDU;
    extern __shared__ uint16_t smh[];
    uint32_t* U    = reinterpret_cast<uint32_t*>(smh);
    uint32_t* AhiU = U;
    uint32_t* AloU = U + PA;
    uint32_t* B1h  = U + 2 * PA;     // W1, later W3
    uint32_t* B1l  = U + 3 * PA;
    uint32_t* B2h  = U + 4 * PA;
    uint32_t* B2l  = U + 5 * PA;

    const int tid  = threadIdx.x;
    const int wid  = tid >> 5;
    const int lane = tid & 31;
    const int wm   = wid & 3;
    const int wn   = wid >> 2;
    const int row0 = blockIdx.x * 128;
    const int qr   = lane >> 2;
    const int qc   = lane & 3;

    #pragma unroll
    for (int it = 0; it < 8; ++it) {
        int idx = tid + it * 512;
        int r = idx >> 5, c4 = idx & 31;
        int row = row0 + r;
        float4 v = make_float4(0.f, 0.f, 0.f, 0.f);
        if (row < N) v = reinterpret_cast<const float4*>(A)[(size_t)row * 32 + c4];
        uint32_t p01, p23, l01, l23;
        split4(v, p01, p23, l01, l23);
        int o = r * LDU + c4 * 2;
        AhiU[o] = p01; AhiU[o + 1] = p23;
        AloU[o] = l01; AloU[o + 1] = l23;
    }
    stage_w<128>(W1, B1h, B1l, tid);
    stage_w<128>(W2, B2h, B2l, tid);
    __syncthreads();

    uint32_t sb;
    asm("{ .reg .u64 t; cvta.to.shared.u64 t, %1; cvt.u32.u64 %0, t; }" : "=r"(sb) : "l"(smh));
    const int m  = lane >> 3;
    const int mr = ((m >> 1) << 3) + (lane & 7);
    const uint32_t mc = (uint32_t)(m & 1) * 16u;
    const uint32_t oAlo = (uint32_t)PA * 4u;
    const uint32_t aBH0 = sb + (uint32_t)(wm * 32 + 0  + mr) * ROWB + mc;
    const uint32_t aBH1 = sb + (uint32_t)(wm * 32 + 16 + mr) * ROWB + mc;
    const uint32_t oB1 = (uint32_t)(2 * PA) * 4u;
    const uint32_t oB2 = (uint32_t)(4 * PA) * 4u;

    // ---- GEMM1 (W1, relu) ----
    {
        float acc[8][4];
        #pragma unroll
        for (int i = 0; i < 8; ++i)
            #pragma unroll
            for (int c = 0; c < 4; ++c) acc[i][c] = 0.f;
        uint32_t bB[2], bL[2];
        #pragma unroll
        for (int t = 0; t < 2; ++t) {
            bB[t] = sb + oB1 + (uint32_t)(wn * 32 + t * 16 + mr) * ROWB + mc;
            bL[t] = bB[t] + oAlo;
        }
        bf16_mainloop<2>(aBH0, aBH1, aBH0 + oAlo, aBH1 + oAlo, bB, bL, acc);
        __syncthreads();                       // A + W1 reads done
        write_mid<true>(acc, b1, wm, wn, qr, qc, AhiU, AloU);
        stage_w<NOUT3>(W3, B1h, B1l, tid);     // restage W3 over W1
    }
    __syncthreads();

    // ---- GEMM2 (W2, R2) ----
    {
        float acc[8][4];
        #pragma unroll
        for (int i = 0; i < 8; ++i)
            #pragma unroll
            for (int c = 0; c < 4; ++c) acc[i][c] = 0.f;
        uint32_t bB[2], bL[2];
        #pragma unroll
        for (int t = 0; t < 2; ++t) {
            bB[t] = sb + oB2 + (uint32_t)(wn * 32 + t * 16 + mr) * ROWB + mc;
            bL[t] = bB[t] + oAlo;
        }
        bf16_mainloop<2>(aBH0, aBH1, aBH0 + oAlo, aBH1 + oAlo, bB, bL, acc);
        __syncthreads();                       // mid1 reads done
        write_mid<R2>(acc, b2, wm, wn, qr, qc, AhiU, AloU);
    }
    __syncthreads();

    // ---- GEMM3 (W3, NOUT3, R3) ----
    constexpr int NC3 = NOUT3 / 4;
    constexpr int NT3 = NC3 / 16;
    constexpr int NI3 = NT3 * 2;
    float acc3[2 * NI3][4];
    #pragma unroll
    for (int i = 0; i < 2 * NI3; ++i)
        #pragma unroll
        for (int c = 0; c < 4; ++c) acc3[i][c] = 0.f;
    uint32_t bB3[NT3], bL3[NT3];
    #pragma unroll
    for (int t = 0; t < NT3; ++t) {
        bB3[t] = sb + oB1 + (uint32_t)(wn * NC3 + t * 16 + mr) * ROWB + mc;
        bL3[t] = bB3[t] + oAlo;
    }
    bf16_mainloop<NT3>(aBH0, aBH1, aBH0 + oAlo, aBH1 + oAlo, bB3, bL3, acc3);

    const int rbase = row0 + wm * 32 + qr;
    const int cbase = wn * NC3 + qc * 2;
    #pragma unroll
    for (int ni = 0; ni < NI3; ++ni) {
        int c = cbase + ni * 8;
        float b0 = __ldg(b3 + c), b1v = __ldg(b3 + c + 1);
        #pragma unroll
        for (int mi = 0; mi < 2; ++mi) {
            const float* a = acc3[mi * NI3 + ni];
            int r = rbase + mi * 16;
            float v0 = a[0] + b0, v1 = a[1] + b1v, v2 = a[2] + b0, v3 = a[3] + b1v;
            if (R3) {
                v0 = fmaxf(v0, 0.f); v1 = fmaxf(v1, 0.f);
                v2 = fmaxf(v2, 0.f); v3 = fmaxf(v3, 0.f);
            }
            if (r < N)
                *reinterpret_cast<float2*>(out + (size_t)r * NOUT3 + c) = make_float2(v0, v1);
            if (r + 8 < N)
                *reinterpret_cast<float2*>(out + (size_t)(r + 8) * NOUT3 + c) = make_float2(v2, v3);
        }
    }
}

// ---------------- CSR build ---------------------------------------------------
__global__ void zero_int_kernel(int* p, int n) {
    int i = blockIdx.x * blockDim.x + threadIdx.x;
    if (i < n) p[i] = 0;
}
__global__ void hist_kernel(const int* __restrict__ dst, int E, int* __restrict__ deg) {
    int i = blockIdx.x * blockDim.x + threadIdx.x;
    if (i < E) atomicAdd(&deg[dst[i]], 1);
}
__global__ void csr_scan1(const int* __restrict__ deg, int* __restrict__ off,
                          int* __restrict__ bsum, float* __restrict__ invd,
                          int* __restrict__ cnt, int n) {
    __shared__ int s[1024];
    int g = blockIdx.x * 1024 + threadIdx.x;
    int v = (g < n) ? deg[g] : 0;
    if (g < n) { invd[g] = 1.0f / fmaxf((float)v, 1.0f); cnt[g] = 0; }
    s[threadIdx.x] = v;
    __syncthreads();
    #pragma unroll
    for (int d = 1; d < 1024; d <<= 1) {
        int t = (threadIdx.x >= d) ? s[threadIdx.x - d] : 0;
        __syncthreads();
        s[threadIdx.x] += t;
        __syncthreads();
    }
    if (g < n) off[g + 1] = s[threadIdx.x];
    if (threadIdx.x == 1023) bsum[blockIdx.x] = s[1023];
}
__global__ void csr_scan2(int* bsum, int nb) {
    __shared__ int s[128];
    int v = (threadIdx.x < nb) ? bsum[threadIdx.x] : 0;
    s[threadIdx.x] = v;
    __syncthreads();
    #pragma unroll
    for (int d = 1; d < 128; d <<= 1) {
        int t = (threadIdx.x >= d) ? s[threadIdx.x - d] : 0;
        __syncthreads();
        s[threadIdx.x] += t;
        __syncthreads();
    }
    if (threadIdx.x < nb) bsum[threadIdx.x] = s[threadIdx.x] - v;  // exclusive
}
__global__ void csr_scan3(int* __restrict__ off, const int* __restrict__ bsum, int n) {
    int g = blockIdx.x * 1024 + threadIdx.x;
    if (g < n) off[g + 1] += bsum[blockIdx.x];
    if (g == 0) off[0] = 0;
}
__global__ void csr_fill(const int* __restrict__ src, const int* __restrict__ dst,
                         const int* __restrict__ off, int* __restrict__ cnt,
                         int* __restrict__ csrc, int E) {
    int i = blockIdx.x * blockDim.x + threadIdx.x;
    if (i < E) {
        int d = dst[i];
        int p = off[d] + atomicAdd(&cnt[d], 1);
        csrc[p] = src[i];
    }
}

// ---------------- fused mean-aggregate: out = h + mean_in(h) ------------------
// one warp per node; 4 independent edge gathers in flight per iteration
__global__ void aggregate_kernel(const float* __restrict__ h, const int* __restrict__ off,
                                 const int* __restrict__ csrc, const float* __restrict__ invd,
                                 float* __restrict__ out, int N)
{
    int wid  = threadIdx.x >> 5;
    int lane = threadIdx.x & 31;
    int node = blockIdx.x * (blockDim.x >> 5) + wid;
    if (node >= N) return;
    int beg = off[node], end = off[node + 1];
    float4 acc = make_float4(0.f, 0.f, 0.f, 0.f);
    const float4* h4 = reinterpret_cast<const float4*>(h);
    int e = beg;
    for (; e + 3 < end; e += 4) {
        int s0 = __ldg(csrc + e),     s1 = __ldg(csrc + e + 1);
        int s2 = __ldg(csrc + e + 2), s3 = __ldg(csrc + e + 3);
        float4 v0 = __ldg(h4 + s0 * 32 + lane);
        float4 v1 = __ldg(h4 + s1 * 32 + lane);
        float4 v2 = __ldg(h4 + s2 * 32 + lane);
        float4 v3 = __ldg(h4 + s3 * 32 + lane);
        acc.x += (v0.x + v1.x) + (v2.x + v3.x);
        acc.y += (v0.y + v1.y) + (v2.y + v3.y);
        acc.z += (v0.z + v1.z) + (v2.z + v3.z);
        acc.w += (v0.w + v1.w) + (v2.w + v3.w);
    }
    for (; e < end; ++e) {
        int s0 = __ldg(csrc + e);
        float4 v0 = __ldg(h4 + s0 * 32 + lane);
        acc.x += v0.x; acc.y += v0.y; acc.z += v0.z; acc.w += v0.w;
    }
    float iv = invd[node];
    float4 b = __ldg(h4 + node * 32 + lane);
    reinterpret_cast<float4*>(out)[node * 32 + lane] =
        make_float4(b.x + acc.x * iv, b.y + acc.y * iv,
                    b.z + acc.z * iv, b.w + acc.w * iv);
}

// ---------------- launch -----------------------------------------------------
extern "C" void kernel_launch(void* const* d_in, const int* in_sizes, int n_in,
                              void* d_out, int out_size)
{
    const float* x   = (const float*)d_in[0];
    const int*   src = (const int*)  d_in[1];
    const int*   dst = (const int*)  d_in[2];
    const float* W1  = (const float*)d_in[3];
    const float* b1  = (const float*)d_in[4];
    const float* W2  = (const float*)d_in[5];
    const float* b2  = (const float*)d_in[6];
    const float* W3  = (const float*)d_in[7];
    const float* b3  = (const float*)d_in[8];
    const float* Wo1 = (const float*)d_in[9];
    const float* bo1 = (const float*)d_in[10];
    const float* Wo2 = (const float*)d_in[11];
    const float* bo2 = (const float*)d_in[12];
    float* out = (float*)d_out;

    const int N = in_sizes[0] / FD;    // 100000
    const int E = in_sizes[1];         // 800000

    float *bufA, *bufB, *invd;
    int *deg, *off, *cnt, *bsum, *csrc;
    cudaGetSymbolAddress((void**)&bufA, g_bufA);
    cudaGetSymbolAddress((void**)&bufB, g_bufB);
    cudaGetSymbolAddress((void**)&invd, g_invdeg);
    cudaGetSymbolAddress((void**)&deg,  g_deg);
    cudaGetSymbolAddress((void**)&off,  g_off);
    cudaGetSymbolAddress((void**)&cnt,  g_cnt);
    cudaGetSymbolAddress((void**)&bsum, g_bsum);
    cudaGetSymbolAddress((void**)&csrc, g_csrc);

    // side stream + fork/join events (created once; capture-safe)
    static cudaStream_t sCSR = nullptr;
    static cudaEvent_t  evFork = nullptr, evJoin = nullptr;
    if (!sCSR) {
        cudaStreamCreateWithFlags(&sCSR, cudaStreamNonBlocking);
        cudaEventCreateWithFlags(&evFork, cudaEventDisableTiming);
        cudaEventCreateWithFlags(&evJoin, cudaEventDisableTiming);
    }

    const int smemF = 6 * 128 * 136 * 2;                  // 208896
    cudaFuncSetAttribute(gemm_fused2, cudaFuncAttributeMaxDynamicSharedMemorySize, smemF);
    cudaFuncSetAttribute(gemm_fused3<false, 128, true>, cudaFuncAttributeMaxDynamicSharedMemorySize, smemF);
    cudaFuncSetAttribute(gemm_fused3<true,  64,  false>, cudaFuncAttributeMaxDynamicSharedMemorySize, smemF);

    const int gb2 = (N + 127) / 128;              // 782 (128-row tiles)
    const int nb  = (N + 1023) / 1024;            // 98 scan blocks
    const int ag  = (N + 7) / 8;                  // aggregate: 8 warps/block

    // ---- fork: CSR build on side stream, concurrent with fused2 ----
    cudaEventRecord(evFork, 0);
    cudaStreamWaitEvent(sCSR, evFork, 0);

    zero_int_kernel<<<(N + 255) / 256, 256, 0, sCSR>>>(deg, N);
    hist_kernel<<<(E + 255) / 256, 256, 0, sCSR>>>(dst, E, deg);
    csr_scan1<<<nb, 1024, 0, sCSR>>>(deg, off, bsum, invd, cnt, N);
    csr_scan2<<<1, 128, 0, sCSR>>>(bsum, nb);
    csr_scan3<<<nb, 1024, 0, sCSR>>>(off, bsum, N);
    csr_fill<<<(E + 255) / 256, 256, 0, sCSR>>>(src, dst, off, cnt, csrc, E);
    cudaEventRecord(evJoin, sCSR);

    // x2 = lin(relu(lin(x,W1,b1)),W2,b2)   [runs concurrent with CSR build]
    gemm_fused2<<<gb2, 512, smemF>>>(x, W1, b1, W2, b2, bufA, N);

    // ---- join before first aggregate ----
    cudaStreamWaitEvent(0, evJoin, 0);

    // h = x2 + mean_agg(x2)
    aggregate_kernel<<<ag, 256>>>(bufA, off, csrc, invd, bufB, N);

    // h = relu(lin( lin(relu(lin(h,W1,b1)),W2,b2), W3,b3))
    gemm_fused3<false, 128, true><<<gb2, 512, smemF>>>(bufB, W1, b1, W2, b2, W3, b3, bufA, N);

    // h = h + mean_agg(h)
    aggregate_kernel<<<ag, 256>>>(bufA, off, csrc, invd, bufB, N);

    // out = lin( relu(lin( relu(lin(h,W3,b3)), Wo1,bo1)), Wo2,bo2)
    gemm_fused3<true, 64, false><<<gb2, 512, smemF>>>(bufB, W3, b3, Wo1, bo1, Wo2, bo2, out, N);
}